// round 5
// baseline (speedup 1.0000x reference)
#include <cuda_runtime.h>
#include <cstdint>

// Problem dims (fixed by the dataset)
#define N_NODES 50000
#define N_EDGES 800000
#define E_TOT   850000   // + self loops
#define IN0     20
#define HID     64
#define OUTC    128
#define TB      256

// ---------------- scratch (device globals; no allocation allowed) ----------
__device__ __align__(16) float g_feat0[N_NODES * IN0];   //  4.0 MB
__device__ __align__(16) float g_h[N_NODES * 256];       // 51.2 MB
__device__ __align__(16) float g_sA[N_NODES * 4];
__device__ __align__(16) float g_sB[N_NODES * 4];
__device__ __align__(16) float g_r[E_TOT * 4];           // 13.6 MB (exp-values)
__device__ __align__(16) float g_accum[N_NODES * HID];   // 12.8 MB
__device__ __align__(16) float g_Z[12];                  // L0:0-3  L1:4-7  L2:8
// CSR by destination (identical for all 3 layers; rebuilt every launch)
__device__ int g_deg[N_NODES];        // static zero-init; re-zeroed by scan each launch
__device__ int g_off[N_NODES + 1];
__device__ int g_cur[N_NODES];
__device__ int g_csr_src[E_TOT];
__device__ int g_csr_eid[E_TOT];

// ---------------- kernel 1: feat build + degree histogram + Z reset --------
// work ranges: [0, N*IN0) feat | [.., +E) edge hist | [.., +N) self loops | 12 Z
#define W_FEAT (N_NODES * IN0)
#define W_HIST (W_FEAT + N_EDGES)
#define W_LOOP (W_HIST + N_NODES)
#define W_TOT  (W_LOOP + 12)
__global__ void feat0hist_kernel(const float* __restrict__ x,
                                 const int*   __restrict__ jt,
                                 const float* __restrict__ emb,
                                 const int*   __restrict__ ei) {
    int i = blockIdx.x * blockDim.x + threadIdx.x;
    if (i < W_FEAT) {
        int n = i / IN0, k = i - n * IN0;
        float v;
        if (k < 4) v = x[n * 4 + k];
        else       v = __ldg(&emb[jt[n] * 16 + (k - 4)]);
        g_feat0[i] = v;
    } else if (i < W_HIST) {
        int e = i - W_FEAT;
        atomicAdd(&g_deg[__ldg(&ei[N_EDGES + e])], 1);
    } else if (i < W_LOOP) {
        atomicAdd(&g_deg[i - W_HIST], 1);          // self loop per node
    } else if (i < W_TOT) {
        g_Z[i - W_LOOP] = 0.f;
    }
}

// ---------------- kernel 2: exclusive scan of degrees (1 block) ------------
__global__ void scan_kernel() {
    const int CH = (N_NODES + 1023) / 1024;        // 49
    __shared__ int ssum[1024];
    int t = threadIdx.x;
    int base = t * CH;
    int s = 0;
    for (int j = 0; j < CH; j++) {
        int idx = base + j;
        if (idx < N_NODES) s += g_deg[idx];
    }
    ssum[t] = s;
    __syncthreads();
    // Hillis-Steele inclusive scan (read-old / barrier / write)
    for (int off = 1; off < 1024; off <<= 1) {
        int v = (t >= off) ? ssum[t - off] : 0;
        __syncthreads();
        ssum[t] += v;
        __syncthreads();
    }
    int run = ssum[t] - s;                         // exclusive prefix for this chunk
    for (int j = 0; j < CH; j++) {
        int idx = base + j;
        if (idx < N_NODES) {
            int d = g_deg[idx];
            g_off[idx] = run;
            g_cur[idx] = run;
            g_deg[idx] = 0;                        // re-zero for next launch
            run += d;
        }
    }
    if (t == 1023) g_off[N_NODES] = ssum[1023];    // == E_TOT
}

// ---------------- kernel 3: CSR scatter ------------------------------------
__global__ void scatter_kernel(const int* __restrict__ ei) {
    int e = blockIdx.x * blockDim.x + threadIdx.x;
    if (e >= E_TOT) return;
    int s, d;
    if (e < N_EDGES) { s = __ldg(&ei[e]); d = __ldg(&ei[N_EDGES + e]); }
    else             { s = d = e - N_EDGES; }
    int pos = atomicAdd(&g_cur[d], 1);
    g_csr_src[pos] = s;
    g_csr_eid[pos] = e;
}

// ---------------- fused GEMM + attention scores (H=4, OUT=256) -------------
// blockDim = 256, 8 node rows per block. Thread t owns output column t
// (head = t/64). After the matmul, per-node scores s = h.a_src / h.a_dst are
// reduced in-block and written, so h never has to be re-read.
template<int IN, bool ELU>
__global__ void gemm_s4_kernel(const float* __restrict__ feat,
                               const float* __restrict__ W,
                               const float* __restrict__ asrc,
                               const float* __restrict__ adst,
                               float* __restrict__ out) {
    constexpr int ROWS = 8;
    __shared__ __align__(16) float sfeat[ROWS * IN];
    __shared__ float sredS[ROWS][8], sredD[ROWS][8];
    int t = threadIdx.x, wid = t >> 5, lane = t & 31;
    int row0 = blockIdx.x * ROWS;
    for (int i = t; i < ROWS * IN; i += 256) {
        float v = __ldg(&feat[row0 * IN + i]);
        if (ELU) v = v > 0.f ? v : expm1f(v);
        sfeat[i] = v;
    }
    float wreg[IN];
#pragma unroll
    for (int k = 0; k < IN; k++) wreg[k] = __ldg(&W[t * IN + k]);
    float aval = __ldg(&asrc[t]), bval = __ldg(&adst[t]);
    __syncthreads();
#pragma unroll
    for (int r = 0; r < ROWS; r++) {
        const float4* sf4 = (const float4*)(sfeat + r * IN);
        float acc = 0.f;
#pragma unroll
        for (int k4 = 0; k4 < IN / 4; k4++) {
            float4 f = sf4[k4];
            acc += wreg[4 * k4 + 0] * f.x;
            acc += wreg[4 * k4 + 1] * f.y;
            acc += wreg[4 * k4 + 2] * f.z;
            acc += wreg[4 * k4 + 3] * f.w;
        }
        out[(size_t)(row0 + r) * 256 + t] = acc;
        float ps = acc * aval, pd = acc * bval;
#pragma unroll
        for (int off = 16; off; off >>= 1) {
            ps += __shfl_xor_sync(0xffffffffu, ps, off);
            pd += __shfl_xor_sync(0xffffffffu, pd, off);
        }
        if (lane == 0) { sredS[r][wid] = ps; sredD[r][wid] = pd; }
    }
    __syncthreads();
    if (t < 32) {
        int r = t >> 2, h = t & 3;
        g_sA[(size_t)(row0 + r) * 4 + h] = sredS[r][2 * h] + sredS[r][2 * h + 1];
        g_sB[(size_t)(row0 + r) * 4 + h] = sredD[r][2 * h] + sredD[r][2 * h + 1];
    }
}

// ---------------- fused GEMM + scores (H=1, OUT=128) -----------------------
template<int IN, bool ELU>
__global__ void gemm_s1_kernel(const float* __restrict__ feat,
                               const float* __restrict__ W,
                               const float* __restrict__ asrc,
                               const float* __restrict__ adst,
                               float* __restrict__ out) {
    constexpr int ROWS = 8;
    __shared__ __align__(16) float sfeat[ROWS * IN];
    __shared__ float sredS[ROWS][4], sredD[ROWS][4];
    int t = threadIdx.x, wid = t >> 5, lane = t & 31;
    int row0 = blockIdx.x * ROWS;
    for (int i = t; i < ROWS * IN; i += 128) {
        float v = __ldg(&feat[row0 * IN + i]);
        if (ELU) v = v > 0.f ? v : expm1f(v);
        sfeat[i] = v;
    }
    float wreg[IN];
#pragma unroll
    for (int k = 0; k < IN; k++) wreg[k] = __ldg(&W[t * IN + k]);
    float aval = __ldg(&asrc[t]), bval = __ldg(&adst[t]);
    __syncthreads();
#pragma unroll
    for (int r = 0; r < ROWS; r++) {
        const float4* sf4 = (const float4*)(sfeat + r * IN);
        float acc = 0.f;
#pragma unroll
        for (int k4 = 0; k4 < IN / 4; k4++) {
            float4 f = sf4[k4];
            acc += wreg[4 * k4 + 0] * f.x;
            acc += wreg[4 * k4 + 1] * f.y;
            acc += wreg[4 * k4 + 2] * f.z;
            acc += wreg[4 * k4 + 3] * f.w;
        }
        out[(size_t)(row0 + r) * 128 + t] = acc;
        float ps = acc * aval, pd = acc * bval;
#pragma unroll
        for (int off = 16; off; off >>= 1) {
            ps += __shfl_xor_sync(0xffffffffu, ps, off);
            pd += __shfl_xor_sync(0xffffffffu, pd, off);
        }
        if (lane == 0) { sredS[r][wid] = ps; sredD[r][wid] = pd; }
    }
    __syncthreads();
    if (t < ROWS) {
        g_sA[row0 + t] = sredS[t][0] + sredS[t][1] + sredS[t][2] + sredS[t][3];
        g_sB[row0 + t] = sredD[t][0] + sredD[t][1] + sredD[t][2] + sredD[t][3];
    }
}

// ---------------- fused edge scores + exp + Z-sum (H = 4) ------------------
// No max-subtraction: scores are bounded (|r| < ~20 for this data), exp is
// safe in fp32, softmax result identical up to fp rounding.
__global__ void scoresum4_kernel(const int* __restrict__ ei,
                                 const float* __restrict__ eattr,
                                 const float* __restrict__ We,
                                 int zbase) {
    __shared__ float sWe[16];
    __shared__ float ssum[4];
    if (threadIdx.x < 16) sWe[threadIdx.x] = We[threadIdx.x];
    if (threadIdx.x < 4)  ssum[threadIdx.x] = 0.f;
    __syncthreads();
    float z0 = 0.f, z1 = 0.f, z2 = 0.f, z3 = 0.f;
    int stride = gridDim.x * blockDim.x;
    for (int e = blockIdx.x * blockDim.x + threadIdx.x; e < E_TOT; e += stride) {
        int s, d; float4 ea;
        if (e < N_EDGES) {
            s = __ldg(&ei[e]); d = __ldg(&ei[N_EDGES + e]);
            ea = __ldg((const float4*)eattr + e);
        } else {
            s = d = e - N_EDGES; ea = make_float4(0.f, 0.f, 0.f, 0.f);
        }
        float4 va = __ldg((const float4*)g_sA + d);
        float4 vb = __ldg((const float4*)g_sB + s);
        float r0 = va.x + vb.x + ea.x * sWe[0]  + ea.y * sWe[1]  + ea.z * sWe[2]  + ea.w * sWe[3];
        float r1 = va.y + vb.y + ea.x * sWe[4]  + ea.y * sWe[5]  + ea.z * sWe[6]  + ea.w * sWe[7];
        float r2 = va.z + vb.z + ea.x * sWe[8]  + ea.y * sWe[9]  + ea.z * sWe[10] + ea.w * sWe[11];
        float r3 = va.w + vb.w + ea.x * sWe[12] + ea.y * sWe[13] + ea.z * sWe[14] + ea.w * sWe[15];
        r0 = r0 > 0.f ? r0 : 0.2f * r0;
        r1 = r1 > 0.f ? r1 : 0.2f * r1;
        r2 = r2 > 0.f ? r2 : 0.2f * r2;
        r3 = r3 > 0.f ? r3 : 0.2f * r3;
        float e0 = expf(r0), e1 = expf(r1), e2 = expf(r2), e3 = expf(r3);
        ((float4*)g_r)[e] = make_float4(e0, e1, e2, e3);
        z0 += e0; z1 += e1; z2 += e2; z3 += e3;
    }
#pragma unroll
    for (int off = 16; off; off >>= 1) {
        z0 += __shfl_xor_sync(0xffffffffu, z0, off);
        z1 += __shfl_xor_sync(0xffffffffu, z1, off);
        z2 += __shfl_xor_sync(0xffffffffu, z2, off);
        z3 += __shfl_xor_sync(0xffffffffu, z3, off);
    }
    if ((threadIdx.x & 31) == 0) {
        atomicAdd(&ssum[0], z0); atomicAdd(&ssum[1], z1);
        atomicAdd(&ssum[2], z2); atomicAdd(&ssum[3], z3);
    }
    __syncthreads();
    if (threadIdx.x < 4) atomicAdd(&g_Z[zbase + threadIdx.x], ssum[threadIdx.x]);
}

// ---------------- fused edge scores + exp + Z-sum (H = 1) ------------------
__global__ void scoresum1_kernel(const int* __restrict__ ei,
                                 const float* __restrict__ eattr,
                                 const float* __restrict__ We,
                                 int zbase) {
    __shared__ float sWe[4];
    __shared__ float ssum;
    if (threadIdx.x < 4)  sWe[threadIdx.x] = We[threadIdx.x];
    if (threadIdx.x == 0) ssum = 0.f;
    __syncthreads();
    float z = 0.f;
    int stride = gridDim.x * blockDim.x;
    for (int e = blockIdx.x * blockDim.x + threadIdx.x; e < E_TOT; e += stride) {
        int s, d; float4 ea;
        if (e < N_EDGES) {
            s = __ldg(&ei[e]); d = __ldg(&ei[N_EDGES + e]);
            ea = __ldg((const float4*)eattr + e);
        } else {
            s = d = e - N_EDGES; ea = make_float4(0.f, 0.f, 0.f, 0.f);
        }
        float r = __ldg(&g_sA[d]) + __ldg(&g_sB[s])
                + ea.x * sWe[0] + ea.y * sWe[1] + ea.z * sWe[2] + ea.w * sWe[3];
        r = r > 0.f ? r : 0.2f * r;
        float ev = expf(r);
        g_r[e] = ev;
        z += ev;
    }
#pragma unroll
    for (int off = 16; off; off >>= 1)
        z += __shfl_xor_sync(0xffffffffu, z, off);
    if ((threadIdx.x & 31) == 0) atomicAdd(&ssum, z);
    __syncthreads();
    if (threadIdx.x == 0) atomicAdd(&g_Z[zbase], ssum);
}

// ---------------- CSR edge aggregation (H=4, C=64), atomic-free ------------
// Warp per destination node; head-mean and 1/Z folded in; one coalesced store.
__global__ void edgepass4_csr(const float* __restrict__ hbuf,
                              float* __restrict__ dst, int zbase) {
    int gw   = (blockIdx.x * blockDim.x + threadIdx.x) >> 5;
    int lane = threadIdx.x & 31;
    if (gw >= N_NODES) return;
    float4 Z = *(const float4*)(g_Z + zbase);
    float i0 = 0.25f / Z.x, i1 = 0.25f / Z.y, i2 = 0.25f / Z.z, i3 = 0.25f / Z.w;
    int b = g_off[gw], eEnd = g_off[gw + 1];
    float ax = 0.f, ay = 0.f;
#pragma unroll 4
    for (int i = b; i < eEnd; i++) {
        int s = __ldg(&g_csr_src[i]);
        int e = __ldg(&g_csr_eid[i]);
        float4 rv = __ldg((const float4*)g_r + e);
        const float2* hp = (const float2*)(hbuf + (size_t)s * 256);
        float2 v0 = __ldg(hp + lane);
        float2 v1 = __ldg(hp + 32 + lane);
        float2 v2 = __ldg(hp + 64 + lane);
        float2 v3 = __ldg(hp + 96 + lane);
        float a0 = rv.x * i0, a1 = rv.y * i1, a2 = rv.z * i2, a3 = rv.w * i3;
        ax += a0 * v0.x + a1 * v1.x + a2 * v2.x + a3 * v3.x;
        ay += a0 * v0.y + a1 * v1.y + a2 * v2.y + a3 * v3.y;
    }
    ((float2*)(dst + (size_t)gw * 64))[lane] = make_float2(ax, ay);
}

// ---------------- CSR edge aggregation (H=1, C=128) → d_out ----------------
__global__ void edgepass1_csr(const float* __restrict__ hbuf,
                              float* __restrict__ outp, int zbase) {
    int gw   = (blockIdx.x * blockDim.x + threadIdx.x) >> 5;
    int lane = threadIdx.x & 31;
    if (gw >= N_NODES) return;
    float iz = 1.0f / g_Z[zbase];
    int b = g_off[gw], eEnd = g_off[gw + 1];
    float x0 = 0.f, x1 = 0.f, x2 = 0.f, x3 = 0.f;
#pragma unroll 4
    for (int i = b; i < eEnd; i++) {
        int s = __ldg(&g_csr_src[i]);
        int e = __ldg(&g_csr_eid[i]);
        float a = __ldg(&g_r[e]) * iz;
        float4 v = __ldg((const float4*)(hbuf + (size_t)s * 128) + lane);
        x0 += a * v.x; x1 += a * v.y; x2 += a * v.z; x3 += a * v.w;
    }
    ((float4*)(outp + (size_t)gw * 128))[lane] = make_float4(x0, x1, x2, x3);
}

// ---------------- host -----------------------------------------------------
extern "C" void kernel_launch(void* const* d_in, const int* in_sizes, int n_in,
                              void* d_out, int out_size) {
    (void)in_sizes; (void)n_in; (void)out_size;
    const float* x     = (const float*)d_in[0];
    const int*   ei    = (const int*)  d_in[1];
    const float* eattr = (const float*)d_in[2];
    const int*   jt    = (const int*)  d_in[3];
    const float* emb   = (const float*)d_in[4];
    const float* W0    = (const float*)d_in[5];
    const float* as0   = (const float*)d_in[6];
    const float* ad0   = (const float*)d_in[7];
    const float* We0   = (const float*)d_in[8];
    const float* W1    = (const float*)d_in[9];
    const float* as1   = (const float*)d_in[10];
    const float* ad1   = (const float*)d_in[11];
    const float* We1   = (const float*)d_in[12];
    const float* W2    = (const float*)d_in[13];
    const float* as2   = (const float*)d_in[14];
    const float* ad2   = (const float*)d_in[15];
    const float* We2   = (const float*)d_in[16];
    float* out = (float*)d_out;

    float *p_feat0, *p_h, *p_accum;
    cudaGetSymbolAddress((void**)&p_feat0, g_feat0);
    cudaGetSymbolAddress((void**)&p_h,     g_h);
    cudaGetSymbolAddress((void**)&p_accum, g_accum);

    const int EP_BLOCKS = (N_NODES * 32 + TB - 1) / TB;  // warp per node
    const int SW_BLOCKS = 2048;

    // CSR build + feature prep (3 launches)
    feat0hist_kernel<<<(W_TOT + TB - 1) / TB, TB>>>(x, jt, emb, ei);
    scan_kernel<<<1, 1024>>>();
    scatter_kernel<<<(E_TOT + TB - 1) / TB, TB>>>(ei);

    // ---- layer 0 (H=4, C=64, IN=20) ----
    gemm_s4_kernel<IN0, false><<<N_NODES / 8, 256>>>(p_feat0, W0, as0, ad0, p_h);
    scoresum4_kernel<<<SW_BLOCKS, TB>>>(ei, eattr, We0, 0);
    edgepass4_csr<<<EP_BLOCKS, TB>>>(p_h, p_accum, 0);

    // ---- layer 1 (H=4, C=64, IN=64); ELU fused into gemm feature load ----
    gemm_s4_kernel<HID, true><<<N_NODES / 8, 256>>>(p_accum, W1, as1, ad1, p_h);
    scoresum4_kernel<<<SW_BLOCKS, TB>>>(ei, eattr, We1, 4);
    edgepass4_csr<<<EP_BLOCKS, TB>>>(p_h, p_accum, 4);

    // ---- layer 2 (H=1, C=128, IN=64); ELU fused; output -> d_out ----
    gemm_s1_kernel<HID, true><<<N_NODES / 8, 128>>>(p_accum, W2, as2, ad2, p_h);
    scoresum1_kernel<<<SW_BLOCKS, TB>>>(ei, eattr, We2, 8);
    edgepass1_csr<<<EP_BLOCKS, TB>>>(p_h, out, 8);
}

// round 7
// speedup vs baseline: 1.7766x; 1.7766x over previous
#include <cuda_runtime.h>
#include <cstdint>

// Problem dims (fixed by the dataset)
#define N_NODES 50000
#define N_EDGES 800000
#define E_TOT   850000   // + self loops
#define IN0     20
#define HID     64
#define OUTC    128
#define TB      256

// ---------------- scratch (device globals; no allocation allowed) ----------
__device__ __align__(16) float g_feat0[N_NODES * IN0];   //  4.0 MB
__device__ __align__(16) float g_h[N_NODES * 256];       // 51.2 MB
__device__ __align__(16) float g_sA[N_NODES * 4];
__device__ __align__(16) float g_sB[N_NODES * 4];
__device__ __align__(16) float g_r[E_TOT * 4];           // 13.6 MB (exp-values)
__device__ __align__(16) float g_accum[N_NODES * HID];   // 12.8 MB
__device__ __align__(16) float g_Z[12];                  // L0:0-3  L1:4-7  L2:8
// CSR by destination (identical for all 3 layers; rebuilt every launch)
__device__ int g_deg[N_NODES];        // static zero-init; re-zeroed by scan each launch
__device__ int g_off[N_NODES + 1];
__device__ int g_cur[N_NODES];
__device__ int g_csr_src[E_TOT];
__device__ int g_csr_eid[E_TOT];

// ---------------- kernel 1: feat build + degree histogram + Z reset --------
#define W_FEAT (N_NODES * IN0)
#define W_HIST (W_FEAT + N_EDGES)
#define W_LOOP (W_HIST + N_NODES)
#define W_TOT  (W_LOOP + 12)
__global__ void feat0hist_kernel(const float* __restrict__ x,
                                 const int*   __restrict__ jt,
                                 const float* __restrict__ emb,
                                 const int*   __restrict__ ei) {
    int i = blockIdx.x * blockDim.x + threadIdx.x;
    if (i < W_FEAT) {
        int n = i / IN0, k = i - n * IN0;
        float v;
        if (k < 4) v = x[n * 4 + k];
        else       v = __ldg(&emb[jt[n] * 16 + (k - 4)]);
        g_feat0[i] = v;
    } else if (i < W_HIST) {
        int e = i - W_FEAT;
        atomicAdd(&g_deg[__ldg(&ei[N_EDGES + e])], 1);
    } else if (i < W_LOOP) {
        atomicAdd(&g_deg[i - W_HIST], 1);          // self loop per node
    } else if (i < W_TOT) {
        g_Z[i - W_LOOP] = 0.f;
    }
}

// ---------------- kernel 2: exclusive scan of degrees (1 block) ------------
__global__ void scan_kernel() {
    const int CH = (N_NODES + 1023) / 1024;        // 49
    __shared__ int ssum[1024];
    int t = threadIdx.x;
    int base = t * CH;
    int s = 0;
    for (int j = 0; j < CH; j++) {
        int idx = base + j;
        if (idx < N_NODES) s += g_deg[idx];
    }
    ssum[t] = s;
    __syncthreads();
    for (int off = 1; off < 1024; off <<= 1) {
        int v = (t >= off) ? ssum[t - off] : 0;
        __syncthreads();
        ssum[t] += v;
        __syncthreads();
    }
    int run = ssum[t] - s;
    for (int j = 0; j < CH; j++) {
        int idx = base + j;
        if (idx < N_NODES) {
            int d = g_deg[idx];
            g_off[idx] = run;
            g_cur[idx] = run;
            g_deg[idx] = 0;
            run += d;
        }
    }
    if (t == 1023) g_off[N_NODES] = ssum[1023];    // == E_TOT
}

// ---------------- kernel 3: CSR scatter ------------------------------------
__global__ void scatter_kernel(const int* __restrict__ ei) {
    int e = blockIdx.x * blockDim.x + threadIdx.x;
    if (e >= E_TOT) return;
    int s, d;
    if (e < N_EDGES) { s = __ldg(&ei[e]); d = __ldg(&ei[N_EDGES + e]); }
    else             { s = d = e - N_EDGES; }
    int pos = atomicAdd(&g_cur[d], 1);
    g_csr_src[pos] = s;
    g_csr_eid[pos] = e;
}

// ---------------- fused GEMM + attention scores (H=4, OUT=256) -------------
// blockDim = 256. ROWS=25 node rows per block (50000 = 2000*25).
// W is staged into smem with COALESCED loads (fix for the measured L1
// wavefront storm from strided per-thread W reads), then copied to registers
// through a conflict-free odd-pitch layout. Inner loop: broadcast float4 LDS
// of features + FFMA, 2 accumulators for ILP. Per-node scores s = h.a_src /
// h.a_dst reduced in-block so h is never re-read.
template<int IN, int CH, bool ELU>
__global__ void gemm_s4_kernel(const float* __restrict__ feat,
                               const float* __restrict__ W,
                               const float* __restrict__ asrc,
                               const float* __restrict__ adst,
                               float* __restrict__ out) {
    constexpr int ROWS = 25;
    constexpr int NCHUNK = IN / CH;
    __shared__ __align__(16) float sW[256 * (CH + 1)];
    __shared__ __align__(16) float sfeat[ROWS * IN];
    __shared__ float sredS[ROWS][8], sredD[ROWS][8];
    int t = threadIdx.x, wid = t >> 5, lane = t & 31;
    int row0 = blockIdx.x * ROWS;
    // stage features (coalesced), ELU fused
    for (int i = t; i < ROWS * IN; i += 256) {
        float v = __ldg(&feat[row0 * IN + i]);
        if (ELU) v = v > 0.f ? v : expm1f(v);
        sfeat[i] = v;
    }
    // stage W chunk-by-chunk (coalesced LDG) and copy to regs (conflict-free)
    float wreg[IN];
#pragma unroll
    for (int c = 0; c < NCHUNK; c++) {
        if (c) __syncthreads();                     // protect previous chunk
        for (int idx = t; idx < 256 * CH; idx += 256) {
            int row = idx / CH, kk = idx - row * CH;
            sW[row * (CH + 1) + kk] = __ldg(&W[row * IN + c * CH + kk]);
        }
        __syncthreads();
#pragma unroll
        for (int kk = 0; kk < CH; kk++)
            wreg[c * CH + kk] = sW[t * (CH + 1) + kk];
    }
    float aval = __ldg(&asrc[t]), bval = __ldg(&adst[t]);
    __syncthreads();
#pragma unroll 5
    for (int r = 0; r < ROWS; r++) {
        const float4* sf4 = (const float4*)(sfeat + r * IN);
        float acc0 = 0.f, acc1 = 0.f;
#pragma unroll
        for (int k4 = 0; k4 < IN / 4; k4++) {
            float4 f = sf4[k4];
            if (k4 & 1) {
                acc1 += wreg[4 * k4 + 0] * f.x;
                acc1 += wreg[4 * k4 + 1] * f.y;
                acc1 += wreg[4 * k4 + 2] * f.z;
                acc1 += wreg[4 * k4 + 3] * f.w;
            } else {
                acc0 += wreg[4 * k4 + 0] * f.x;
                acc0 += wreg[4 * k4 + 1] * f.y;
                acc0 += wreg[4 * k4 + 2] * f.z;
                acc0 += wreg[4 * k4 + 3] * f.w;
            }
        }
        float acc = acc0 + acc1;
        out[(size_t)(row0 + r) * 256 + t] = acc;
        float ps = acc * aval, pd = acc * bval;
#pragma unroll
        for (int off = 16; off; off >>= 1) {
            ps += __shfl_xor_sync(0xffffffffu, ps, off);
            pd += __shfl_xor_sync(0xffffffffu, pd, off);
        }
        if (lane == 0) { sredS[r][wid] = ps; sredD[r][wid] = pd; }
    }
    __syncthreads();
    if (t < ROWS * 4) {
        int r = t >> 2, h = t & 3;
        g_sA[(size_t)(row0 + r) * 4 + h] = sredS[r][2 * h] + sredS[r][2 * h + 1];
        g_sB[(size_t)(row0 + r) * 4 + h] = sredD[r][2 * h] + sredD[r][2 * h + 1];
    }
}

// ---------------- fused GEMM + scores (H=1, OUT=128) -----------------------
template<int IN, int CH, bool ELU>
__global__ void gemm_s1_kernel(const float* __restrict__ feat,
                               const float* __restrict__ W,
                               const float* __restrict__ asrc,
                               const float* __restrict__ adst,
                               float* __restrict__ out) {
    constexpr int ROWS = 25;
    constexpr int NCHUNK = IN / CH;
    __shared__ __align__(16) float sW[128 * (CH + 1)];
    __shared__ __align__(16) float sfeat[ROWS * IN];
    __shared__ float sredS[ROWS][4], sredD[ROWS][4];
    int t = threadIdx.x, wid = t >> 5, lane = t & 31;
    int row0 = blockIdx.x * ROWS;
    for (int i = t; i < ROWS * IN; i += 128) {
        float v = __ldg(&feat[row0 * IN + i]);
        if (ELU) v = v > 0.f ? v : expm1f(v);
        sfeat[i] = v;
    }
    float wreg[IN];
#pragma unroll
    for (int c = 0; c < NCHUNK; c++) {
        if (c) __syncthreads();
        for (int idx = t; idx < 128 * CH; idx += 128) {
            int row = idx / CH, kk = idx - row * CH;
            sW[row * (CH + 1) + kk] = __ldg(&W[row * IN + c * CH + kk]);
        }
        __syncthreads();
#pragma unroll
        for (int kk = 0; kk < CH; kk++)
            wreg[c * CH + kk] = sW[t * (CH + 1) + kk];
    }
    float aval = __ldg(&asrc[t]), bval = __ldg(&adst[t]);
    __syncthreads();
#pragma unroll 5
    for (int r = 0; r < ROWS; r++) {
        const float4* sf4 = (const float4*)(sfeat + r * IN);
        float acc0 = 0.f, acc1 = 0.f;
#pragma unroll
        for (int k4 = 0; k4 < IN / 4; k4++) {
            float4 f = sf4[k4];
            if (k4 & 1) {
                acc1 += wreg[4 * k4 + 0] * f.x;
                acc1 += wreg[4 * k4 + 1] * f.y;
                acc1 += wreg[4 * k4 + 2] * f.z;
                acc1 += wreg[4 * k4 + 3] * f.w;
            } else {
                acc0 += wreg[4 * k4 + 0] * f.x;
                acc0 += wreg[4 * k4 + 1] * f.y;
                acc0 += wreg[4 * k4 + 2] * f.z;
                acc0 += wreg[4 * k4 + 3] * f.w;
            }
        }
        float acc = acc0 + acc1;
        out[(size_t)(row0 + r) * 128 + t] = acc;
        float ps = acc * aval, pd = acc * bval;
#pragma unroll
        for (int off = 16; off; off >>= 1) {
            ps += __shfl_xor_sync(0xffffffffu, ps, off);
            pd += __shfl_xor_sync(0xffffffffu, pd, off);
        }
        if (lane == 0) { sredS[r][wid] = ps; sredD[r][wid] = pd; }
    }
    __syncthreads();
    if (t < ROWS) {
        g_sA[row0 + t] = sredS[t][0] + sredS[t][1] + sredS[t][2] + sredS[t][3];
        g_sB[row0 + t] = sredD[t][0] + sredD[t][1] + sredD[t][2] + sredD[t][3];
    }
}

// ---------------- fused edge scores + exp + Z-sum (H = 4) ------------------
__global__ void scoresum4_kernel(const int* __restrict__ ei,
                                 const float* __restrict__ eattr,
                                 const float* __restrict__ We,
                                 int zbase) {
    __shared__ float sWe[16];
    __shared__ float ssum[4];
    if (threadIdx.x < 16) sWe[threadIdx.x] = We[threadIdx.x];
    if (threadIdx.x < 4)  ssum[threadIdx.x] = 0.f;
    __syncthreads();
    float z0 = 0.f, z1 = 0.f, z2 = 0.f, z3 = 0.f;
    int stride = gridDim.x * blockDim.x;
    for (int e = blockIdx.x * blockDim.x + threadIdx.x; e < E_TOT; e += stride) {
        int s, d; float4 ea;
        if (e < N_EDGES) {
            s = __ldg(&ei[e]); d = __ldg(&ei[N_EDGES + e]);
            ea = __ldg((const float4*)eattr + e);
        } else {
            s = d = e - N_EDGES; ea = make_float4(0.f, 0.f, 0.f, 0.f);
        }
        float4 va = __ldg((const float4*)g_sA + d);
        float4 vb = __ldg((const float4*)g_sB + s);
        float r0 = va.x + vb.x + ea.x * sWe[0]  + ea.y * sWe[1]  + ea.z * sWe[2]  + ea.w * sWe[3];
        float r1 = va.y + vb.y + ea.x * sWe[4]  + ea.y * sWe[5]  + ea.z * sWe[6]  + ea.w * sWe[7];
        float r2 = va.z + vb.z + ea.x * sWe[8]  + ea.y * sWe[9]  + ea.z * sWe[10] + ea.w * sWe[11];
        float r3 = va.w + vb.w + ea.x * sWe[12] + ea.y * sWe[13] + ea.z * sWe[14] + ea.w * sWe[15];
        r0 = r0 > 0.f ? r0 : 0.2f * r0;
        r1 = r1 > 0.f ? r1 : 0.2f * r1;
        r2 = r2 > 0.f ? r2 : 0.2f * r2;
        r3 = r3 > 0.f ? r3 : 0.2f * r3;
        float e0 = expf(r0), e1 = expf(r1), e2 = expf(r2), e3 = expf(r3);
        ((float4*)g_r)[e] = make_float4(e0, e1, e2, e3);
        z0 += e0; z1 += e1; z2 += e2; z3 += e3;
    }
#pragma unroll
    for (int off = 16; off; off >>= 1) {
        z0 += __shfl_xor_sync(0xffffffffu, z0, off);
        z1 += __shfl_xor_sync(0xffffffffu, z1, off);
        z2 += __shfl_xor_sync(0xffffffffu, z2, off);
        z3 += __shfl_xor_sync(0xffffffffu, z3, off);
    }
    if ((threadIdx.x & 31) == 0) {
        atomicAdd(&ssum[0], z0); atomicAdd(&ssum[1], z1);
        atomicAdd(&ssum[2], z2); atomicAdd(&ssum[3], z3);
    }
    __syncthreads();
    if (threadIdx.x < 4) atomicAdd(&g_Z[zbase + threadIdx.x], ssum[threadIdx.x]);
}

// ---------------- fused edge scores + exp + Z-sum (H = 1) ------------------
__global__ void scoresum1_kernel(const int* __restrict__ ei,
                                 const float* __restrict__ eattr,
                                 const float* __restrict__ We,
                                 int zbase) {
    __shared__ float sWe[4];
    __shared__ float ssum;
    if (threadIdx.x < 4)  sWe[threadIdx.x] = We[threadIdx.x];
    if (threadIdx.x == 0) ssum = 0.f;
    __syncthreads();
    float z = 0.f;
    int stride = gridDim.x * blockDim.x;
    for (int e = blockIdx.x * blockDim.x + threadIdx.x; e < E_TOT; e += stride) {
        int s, d; float4 ea;
        if (e < N_EDGES) {
            s = __ldg(&ei[e]); d = __ldg(&ei[N_EDGES + e]);
            ea = __ldg((const float4*)eattr + e);
        } else {
            s = d = e - N_EDGES; ea = make_float4(0.f, 0.f, 0.f, 0.f);
        }
        float r = __ldg(&g_sA[d]) + __ldg(&g_sB[s])
                + ea.x * sWe[0] + ea.y * sWe[1] + ea.z * sWe[2] + ea.w * sWe[3];
        r = r > 0.f ? r : 0.2f * r;
        float ev = expf(r);
        g_r[e] = ev;
        z += ev;
    }
#pragma unroll
    for (int off = 16; off; off >>= 1)
        z += __shfl_xor_sync(0xffffffffu, z, off);
    if ((threadIdx.x & 31) == 0) atomicAdd(&ssum, z);
    __syncthreads();
    if (threadIdx.x == 0) atomicAdd(&g_Z[zbase], ssum);
}

// ---------------- CSR edge aggregation (H=4, C=64), atomic-free ------------
__global__ void edgepass4_csr(const float* __restrict__ hbuf,
                              float* __restrict__ dst, int zbase) {
    int gw   = (blockIdx.x * blockDim.x + threadIdx.x) >> 5;
    int lane = threadIdx.x & 31;
    if (gw >= N_NODES) return;
    float4 Z = *(const float4*)(g_Z + zbase);
    float i0 = 0.25f / Z.x, i1 = 0.25f / Z.y, i2 = 0.25f / Z.z, i3 = 0.25f / Z.w;
    int b = g_off[gw], eEnd = g_off[gw + 1];
    float ax = 0.f, ay = 0.f;
#pragma unroll 4
    for (int i = b; i < eEnd; i++) {
        int s = __ldg(&g_csr_src[i]);
        int e = __ldg(&g_csr_eid[i]);
        float4 rv = __ldg((const float4*)g_r + e);
        const float2* hp = (const float2*)(hbuf + (size_t)s * 256);
        float2 v0 = __ldg(hp + lane);
        float2 v1 = __ldg(hp + 32 + lane);
        float2 v2 = __ldg(hp + 64 + lane);
        float2 v3 = __ldg(hp + 96 + lane);
        float a0 = rv.x * i0, a1 = rv.y * i1, a2 = rv.z * i2, a3 = rv.w * i3;
        ax += a0 * v0.x + a1 * v1.x + a2 * v2.x + a3 * v3.x;
        ay += a0 * v0.y + a1 * v1.y + a2 * v2.y + a3 * v3.y;
    }
    ((float2*)(dst + (size_t)gw * 64))[lane] = make_float2(ax, ay);
}

// ---------------- CSR edge aggregation (H=1, C=128) → d_out ----------------
__global__ void edgepass1_csr(const float* __restrict__ hbuf,
                              float* __restrict__ outp, int zbase) {
    int gw   = (blockIdx.x * blockDim.x + threadIdx.x) >> 5;
    int lane = threadIdx.x & 31;
    if (gw >= N_NODES) return;
    float iz = 1.0f / g_Z[zbase];
    int b = g_off[gw], eEnd = g_off[gw + 1];
    float x0 = 0.f, x1 = 0.f, x2 = 0.f, x3 = 0.f;
#pragma unroll 4
    for (int i = b; i < eEnd; i++) {
        int s = __ldg(&g_csr_src[i]);
        int e = __ldg(&g_csr_eid[i]);
        float a = __ldg(&g_r[e]) * iz;
        float4 v = __ldg((const float4*)(hbuf + (size_t)s * 128) + lane);
        x0 += a * v.x; x1 += a * v.y; x2 += a * v.z; x3 += a * v.w;
    }
    ((float4*)(outp + (size_t)gw * 128))[lane] = make_float4(x0, x1, x2, x3);
}

// ---------------- host -----------------------------------------------------
extern "C" void kernel_launch(void* const* d_in, const int* in_sizes, int n_in,
                              void* d_out, int out_size) {
    (void)in_sizes; (void)n_in; (void)out_size;
    const float* x     = (const float*)d_in[0];
    const int*   ei    = (const int*)  d_in[1];
    const float* eattr = (const float*)d_in[2];
    const int*   jt    = (const int*)  d_in[3];
    const float* emb   = (const float*)d_in[4];
    const float* W0    = (const float*)d_in[5];
    const float* as0   = (const float*)d_in[6];
    const float* ad0   = (const float*)d_in[7];
    const float* We0   = (const float*)d_in[8];
    const float* W1    = (const float*)d_in[9];
    const float* as1   = (const float*)d_in[10];
    const float* ad1   = (const float*)d_in[11];
    const float* We1   = (const float*)d_in[12];
    const float* W2    = (const float*)d_in[13];
    const float* as2   = (const float*)d_in[14];
    const float* ad2   = (const float*)d_in[15];
    const float* We2   = (const float*)d_in[16];
    float* out = (float*)d_out;

    float *p_feat0, *p_h, *p_accum;
    cudaGetSymbolAddress((void**)&p_feat0, g_feat0);
    cudaGetSymbolAddress((void**)&p_h,     g_h);
    cudaGetSymbolAddress((void**)&p_accum, g_accum);

    const int GEMM_BLOCKS = N_NODES / 25;                // 2000, exact
    const int EP_BLOCKS = (N_NODES * 32 + TB - 1) / TB;  // warp per node
    const int SW_BLOCKS = 2048;

    // CSR build + feature prep (3 launches)
    feat0hist_kernel<<<(W_TOT + TB - 1) / TB, TB>>>(x, jt, emb, ei);
    scan_kernel<<<1, 1024>>>();
    scatter_kernel<<<(E_TOT + TB - 1) / TB, TB>>>(ei);

    // ---- layer 0 (H=4, C=64, IN=20) ----
    gemm_s4_kernel<IN0, 20, false><<<GEMM_BLOCKS, 256>>>(p_feat0, W0, as0, ad0, p_h);
    scoresum4_kernel<<<SW_BLOCKS, TB>>>(ei, eattr, We0, 0);
    edgepass4_csr<<<EP_BLOCKS, TB>>>(p_h, p_accum, 0);

    // ---- layer 1 (H=4, C=64, IN=64); ELU fused into gemm feature load ----
    gemm_s4_kernel<HID, 32, true><<<GEMM_BLOCKS, 256>>>(p_accum, W1, as1, ad1, p_h);
    scoresum4_kernel<<<SW_BLOCKS, TB>>>(ei, eattr, We1, 4);
    edgepass4_csr<<<EP_BLOCKS, TB>>>(p_h, p_accum, 4);

    // ---- layer 2 (H=1, C=128, IN=64); ELU fused; output -> d_out ----
    gemm_s1_kernel<HID, 64, true><<<GEMM_BLOCKS, 128>>>(p_accum, W2, as2, ad2, p_h);
    scoresum1_kernel<<<SW_BLOCKS, TB>>>(ei, eattr, We2, 8);
    edgepass1_csr<<<EP_BLOCKS, TB>>>(p_h, out, 8);
}

// round 8
// speedup vs baseline: 1.8784x; 1.0573x over previous
#include <cuda_runtime.h>
#include <cstdint>

// Problem dims (fixed by the dataset)
#define N_NODES 50000
#define N_EDGES 800000
#define E_TOT   850000   // + self loops
#define IN0     20
#define HID     64
#define OUTC    128
#define TB      256

// ---------------- scratch (device globals; no allocation allowed) ----------
__device__ __align__(16) float g_feat0[N_NODES * IN0];   //  4.0 MB
__device__ __align__(16) float g_h[N_NODES * 256];       // 51.2 MB
__device__ __align__(16) float g_sA[N_NODES * 4];
__device__ __align__(16) float g_sB[N_NODES * 4];
__device__ __align__(16) float g_r[E_TOT * 4];           // 13.6 MB (exp-values)
__device__ __align__(16) float g_accum[N_NODES * HID];   // 12.8 MB
__device__ __align__(16) float g_Z[12];                  // L0:0-3  L1:4-7  L2:8
// precomputed score projection vectors  p[h,k] = sum_c W[h*C+c,k] * a[h,c]
// layer0 at [0,80) (h*20+k), layer1 at [80,336) (h*64+k), layer2 at [336,400)
__device__ float g_pA[400];
__device__ float g_pB[400];
// CSR by destination (identical for all 3 layers; rebuilt every launch)
__device__ int g_deg[N_NODES];        // static zero-init; re-zeroed by scan each launch
__device__ int g_off[N_NODES + 1];
__device__ int g_cur[N_NODES];
__device__ int g_csr_src[E_TOT];
__device__ int g_csr_eid[E_TOT];

// ---------------- kernel 1: feat build + hist + Z reset + p-vectors --------
#define W_FEAT (N_NODES * IN0)
#define W_HIST (W_FEAT + N_EDGES)
#define W_LOOP (W_HIST + N_NODES)
#define W_Z    (W_LOOP + 12)
#define W_P0   (W_Z + 80)      // layer0: 80 threads (h=t/20, k=t%20)
#define W_P1   (W_P0 + 256)    // layer1: 256 threads (h=t>>6, k=t&63)
#define W_P2   (W_P1 + 64)     // layer2: 64 threads (k=t)
__global__ void feat0hist_kernel(const float* __restrict__ x,
                                 const int*   __restrict__ jt,
                                 const float* __restrict__ emb,
                                 const int*   __restrict__ ei,
                                 const float* __restrict__ W0,
                                 const float* __restrict__ as0,
                                 const float* __restrict__ ad0,
                                 const float* __restrict__ W1,
                                 const float* __restrict__ as1,
                                 const float* __restrict__ ad1,
                                 const float* __restrict__ W2,
                                 const float* __restrict__ as2,
                                 const float* __restrict__ ad2) {
    int i = blockIdx.x * blockDim.x + threadIdx.x;
    if (i < W_FEAT) {
        int n = i / IN0, k = i - n * IN0;
        float v;
        if (k < 4) v = x[n * 4 + k];
        else       v = __ldg(&emb[jt[n] * 16 + (k - 4)]);
        g_feat0[i] = v;
    } else if (i < W_HIST) {
        int e = i - W_FEAT;
        atomicAdd(&g_deg[__ldg(&ei[N_EDGES + e])], 1);
    } else if (i < W_LOOP) {
        atomicAdd(&g_deg[i - W_HIST], 1);          // self loop per node
    } else if (i < W_Z) {
        g_Z[i - W_LOOP] = 0.f;
    } else if (i < W_P0) {                          // layer0 p-vectors
        int t = i - W_Z, h = t / IN0, k = t - h * IN0;
        float a = 0.f, b = 0.f;
        for (int c = 0; c < HID; c++) {
            float w = __ldg(&W0[(h * HID + c) * IN0 + k]);
            a += w * __ldg(&as0[h * HID + c]);
            b += w * __ldg(&ad0[h * HID + c]);
        }
        g_pA[t] = a; g_pB[t] = b;
    } else if (i < W_P1) {                          // layer1 p-vectors
        int t = i - W_P0, h = t >> 6, k = t & 63;
        float a = 0.f, b = 0.f;
        for (int c = 0; c < HID; c++) {
            float w = __ldg(&W1[(h * HID + c) * HID + k]);
            a += w * __ldg(&as1[h * HID + c]);
            b += w * __ldg(&ad1[h * HID + c]);
        }
        g_pA[80 + t] = a; g_pB[80 + t] = b;
    } else if (i < W_P2) {                          // layer2 p-vectors
        int k = i - W_P1;
        float a = 0.f, b = 0.f;
        for (int c = 0; c < OUTC; c++) {
            float w = __ldg(&W2[c * HID + k]);
            a += w * __ldg(&as2[c]);
            b += w * __ldg(&ad2[c]);
        }
        g_pA[336 + k] = a; g_pB[336 + k] = b;
    }
}

// ---------------- kernel 2: exclusive scan of degrees (1 block) ------------
__global__ void scan_kernel() {
    const int CH = (N_NODES + 1023) / 1024;        // 49
    __shared__ int ssum[1024];
    int t = threadIdx.x;
    int base = t * CH;
    int s = 0;
    for (int j = 0; j < CH; j++) {
        int idx = base + j;
        if (idx < N_NODES) s += g_deg[idx];
    }
    ssum[t] = s;
    __syncthreads();
    for (int off = 1; off < 1024; off <<= 1) {
        int v = (t >= off) ? ssum[t - off] : 0;
        __syncthreads();
        ssum[t] += v;
        __syncthreads();
    }
    int run = ssum[t] - s;
    for (int j = 0; j < CH; j++) {
        int idx = base + j;
        if (idx < N_NODES) {
            int d = g_deg[idx];
            g_off[idx] = run;
            g_cur[idx] = run;
            g_deg[idx] = 0;
            run += d;
        }
    }
    if (t == 1023) g_off[N_NODES] = ssum[1023];    // == E_TOT
}

// ---------------- kernel 3: CSR scatter ------------------------------------
__global__ void scatter_kernel(const int* __restrict__ ei) {
    int e = blockIdx.x * blockDim.x + threadIdx.x;
    if (e >= E_TOT) return;
    int s, d;
    if (e < N_EDGES) { s = __ldg(&ei[e]); d = __ldg(&ei[N_EDGES + e]); }
    else             { s = d = e - N_EDGES; }
    int pos = atomicAdd(&g_cur[d], 1);
    g_csr_src[pos] = s;
    g_csr_eid[pos] = e;
}

// ---------------- fused GEMM + attention scores (H=4, OUT=256) -------------
// blockDim = 256. ROWS=25 node rows per block (50000 = 2000*25).
// W staged coalesced into smem, copied to regs via odd-pitch layout.
// Scores computed as feat . p (precomputed p-vectors) by a 100-thread tail —
// NO warp shuffles (the measured L1/issue load in the previous profile).
template<int IN, int CH, bool ELU, int POFF>
__global__ void gemm_s4_kernel(const float* __restrict__ feat,
                               const float* __restrict__ W,
                               float* __restrict__ out) {
    constexpr int ROWS = 25;
    constexpr int P = IN + 4;                      // padded sfeat pitch
    constexpr int NCHUNK = IN / CH;
    __shared__ __align__(16) float sW[256 * (CH + 1)];
    __shared__ __align__(16) float sfeat[ROWS * P];
    int t = threadIdx.x;
    int row0 = blockIdx.x * ROWS;
    // stage features (coalesced), ELU fused, padded pitch
    for (int i = t; i < ROWS * IN; i += 256) {
        int row = i / IN, k = i - row * IN;
        float v = __ldg(&feat[row0 * IN + i]);
        if (ELU) v = v > 0.f ? v : expm1f(v);
        sfeat[row * P + k] = v;
    }
    // stage W chunk-by-chunk (coalesced LDG) and copy to regs (conflict-free)
    float wreg[IN];
#pragma unroll
    for (int c = 0; c < NCHUNK; c++) {
        if (c) __syncthreads();                     // protect previous chunk
        for (int idx = t; idx < 256 * CH; idx += 256) {
            int row = idx / CH, kk = idx - row * CH;
            sW[row * (CH + 1) + kk] = __ldg(&W[row * IN + c * CH + kk]);
        }
        __syncthreads();
#pragma unroll
        for (int kk = 0; kk < CH; kk++)
            wreg[c * CH + kk] = sW[t * (CH + 1) + kk];
    }
    __syncthreads();
#pragma unroll 5
    for (int r = 0; r < ROWS; r++) {
        const float4* sf4 = (const float4*)(sfeat + r * P);
        float acc0 = 0.f, acc1 = 0.f;
#pragma unroll
        for (int k4 = 0; k4 < IN / 4; k4++) {
            float4 f = sf4[k4];
            if (k4 & 1) {
                acc1 += wreg[4 * k4 + 0] * f.x;
                acc1 += wreg[4 * k4 + 1] * f.y;
                acc1 += wreg[4 * k4 + 2] * f.z;
                acc1 += wreg[4 * k4 + 3] * f.w;
            } else {
                acc0 += wreg[4 * k4 + 0] * f.x;
                acc0 += wreg[4 * k4 + 1] * f.y;
                acc0 += wreg[4 * k4 + 2] * f.z;
                acc0 += wreg[4 * k4 + 3] * f.w;
            }
        }
        out[(size_t)(row0 + r) * 256 + t] = acc0 + acc1;
    }
    // score tail: thread (r,h) computes sA/sB = sfeat[r,:] . p[h,:]
    if (t < ROWS * 4) {
        int r = t >> 2, h = t & 3;
        const float* fr = sfeat + r * P;
        float a0 = 0.f, a1 = 0.f, b0 = 0.f, b1 = 0.f;
#pragma unroll
        for (int k = 0; k < IN; k += 2) {
            float f0 = fr[k], f1 = fr[k + 1];
            a0 += f0 * __ldg(&g_pA[POFF + h * IN + k]);
            a1 += f1 * __ldg(&g_pA[POFF + h * IN + k + 1]);
            b0 += f0 * __ldg(&g_pB[POFF + h * IN + k]);
            b1 += f1 * __ldg(&g_pB[POFF + h * IN + k + 1]);
        }
        g_sA[(size_t)(row0 + r) * 4 + h] = a0 + a1;
        g_sB[(size_t)(row0 + r) * 4 + h] = b0 + b1;
    }
}

// ---------------- fused GEMM + scores (H=1, OUT=128) -----------------------
template<int IN, int CH, bool ELU, int POFF>
__global__ void gemm_s1_kernel(const float* __restrict__ feat,
                               const float* __restrict__ W,
                               float* __restrict__ out) {
    constexpr int ROWS = 25;
    constexpr int P = IN + 4;
    constexpr int NCHUNK = IN / CH;
    __shared__ __align__(16) float sW[128 * (CH + 1)];
    __shared__ __align__(16) float sfeat[ROWS * P];
    int t = threadIdx.x;
    int row0 = blockIdx.x * ROWS;
    for (int i = t; i < ROWS * IN; i += 128) {
        int row = i / IN, k = i - row * IN;
        float v = __ldg(&feat[row0 * IN + i]);
        if (ELU) v = v > 0.f ? v : expm1f(v);
        sfeat[row * P + k] = v;
    }
    float wreg[IN];
#pragma unroll
    for (int c = 0; c < NCHUNK; c++) {
        if (c) __syncthreads();
        for (int idx = t; idx < 128 * CH; idx += 128) {
            int row = idx / CH, kk = idx - row * CH;
            sW[row * (CH + 1) + kk] = __ldg(&W[row * IN + c * CH + kk]);
        }
        __syncthreads();
#pragma unroll
        for (int kk = 0; kk < CH; kk++)
            wreg[c * CH + kk] = sW[t * (CH + 1) + kk];
    }
    __syncthreads();
#pragma unroll 5
    for (int r = 0; r < ROWS; r++) {
        const float4* sf4 = (const float4*)(sfeat + r * P);
        float acc0 = 0.f, acc1 = 0.f;
#pragma unroll
        for (int k4 = 0; k4 < IN / 4; k4++) {
            float4 f = sf4[k4];
            if (k4 & 1) {
                acc1 += wreg[4 * k4 + 0] * f.x;
                acc1 += wreg[4 * k4 + 1] * f.y;
                acc1 += wreg[4 * k4 + 2] * f.z;
                acc1 += wreg[4 * k4 + 3] * f.w;
            } else {
                acc0 += wreg[4 * k4 + 0] * f.x;
                acc0 += wreg[4 * k4 + 1] * f.y;
                acc0 += wreg[4 * k4 + 2] * f.z;
                acc0 += wreg[4 * k4 + 3] * f.w;
            }
        }
        out[(size_t)(row0 + r) * 128 + t] = acc0 + acc1;
    }
    if (t < ROWS) {
        const float* fr = sfeat + t * P;
        float a0 = 0.f, a1 = 0.f, b0 = 0.f, b1 = 0.f;
#pragma unroll
        for (int k = 0; k < IN; k += 2) {
            float f0 = fr[k], f1 = fr[k + 1];
            a0 += f0 * __ldg(&g_pA[POFF + k]);
            a1 += f1 * __ldg(&g_pA[POFF + k + 1]);
            b0 += f0 * __ldg(&g_pB[POFF + k]);
            b1 += f1 * __ldg(&g_pB[POFF + k + 1]);
        }
        g_sA[row0 + t] = a0 + a1;
        g_sB[row0 + t] = b0 + b1;
    }
}

// ---------------- fused edge scores + exp + Z-sum (H = 4) ------------------
__global__ void scoresum4_kernel(const int* __restrict__ ei,
                                 const float* __restrict__ eattr,
                                 const float* __restrict__ We,
                                 int zbase) {
    __shared__ float sWe[16];
    __shared__ float ssum[4];
    if (threadIdx.x < 16) sWe[threadIdx.x] = We[threadIdx.x];
    if (threadIdx.x < 4)  ssum[threadIdx.x] = 0.f;
    __syncthreads();
    float z0 = 0.f, z1 = 0.f, z2 = 0.f, z3 = 0.f;
    int stride = gridDim.x * blockDim.x;
    for (int e = blockIdx.x * blockDim.x + threadIdx.x; e < E_TOT; e += stride) {
        int s, d; float4 ea;
        if (e < N_EDGES) {
            s = __ldg(&ei[e]); d = __ldg(&ei[N_EDGES + e]);
            ea = __ldg((const float4*)eattr + e);
        } else {
            s = d = e - N_EDGES; ea = make_float4(0.f, 0.f, 0.f, 0.f);
        }
        float4 va = __ldg((const float4*)g_sA + d);
        float4 vb = __ldg((const float4*)g_sB + s);
        float r0 = va.x + vb.x + ea.x * sWe[0]  + ea.y * sWe[1]  + ea.z * sWe[2]  + ea.w * sWe[3];
        float r1 = va.y + vb.y + ea.x * sWe[4]  + ea.y * sWe[5]  + ea.z * sWe[6]  + ea.w * sWe[7];
        float r2 = va.z + vb.z + ea.x * sWe[8]  + ea.y * sWe[9]  + ea.z * sWe[10] + ea.w * sWe[11];
        float r3 = va.w + vb.w + ea.x * sWe[12] + ea.y * sWe[13] + ea.z * sWe[14] + ea.w * sWe[15];
        r0 = r0 > 0.f ? r0 : 0.2f * r0;
        r1 = r1 > 0.f ? r1 : 0.2f * r1;
        r2 = r2 > 0.f ? r2 : 0.2f * r2;
        r3 = r3 > 0.f ? r3 : 0.2f * r3;
        float e0 = expf(r0), e1 = expf(r1), e2 = expf(r2), e3 = expf(r3);
        ((float4*)g_r)[e] = make_float4(e0, e1, e2, e3);
        z0 += e0; z1 += e1; z2 += e2; z3 += e3;
    }
#pragma unroll
    for (int off = 16; off; off >>= 1) {
        z0 += __shfl_xor_sync(0xffffffffu, z0, off);
        z1 += __shfl_xor_sync(0xffffffffu, z1, off);
        z2 += __shfl_xor_sync(0xffffffffu, z2, off);
        z3 += __shfl_xor_sync(0xffffffffu, z3, off);
    }
    if ((threadIdx.x & 31) == 0) {
        atomicAdd(&ssum[0], z0); atomicAdd(&ssum[1], z1);
        atomicAdd(&ssum[2], z2); atomicAdd(&ssum[3], z3);
    }
    __syncthreads();
    if (threadIdx.x < 4) atomicAdd(&g_Z[zbase + threadIdx.x], ssum[threadIdx.x]);
}

// ---------------- fused edge scores + exp + Z-sum (H = 1) ------------------
__global__ void scoresum1_kernel(const int* __restrict__ ei,
                                 const float* __restrict__ eattr,
                                 const float* __restrict__ We,
                                 int zbase) {
    __shared__ float sWe[4];
    __shared__ float ssum;
    if (threadIdx.x < 4)  sWe[threadIdx.x] = We[threadIdx.x];
    if (threadIdx.x == 0) ssum = 0.f;
    __syncthreads();
    float z = 0.f;
    int stride = gridDim.x * blockDim.x;
    for (int e = blockIdx.x * blockDim.x + threadIdx.x; e < E_TOT; e += stride) {
        int s, d; float4 ea;
        if (e < N_EDGES) {
            s = __ldg(&ei[e]); d = __ldg(&ei[N_EDGES + e]);
            ea = __ldg((const float4*)eattr + e);
        } else {
            s = d = e - N_EDGES; ea = make_float4(0.f, 0.f, 0.f, 0.f);
        }
        float r = __ldg(&g_sA[d]) + __ldg(&g_sB[s])
                + ea.x * sWe[0] + ea.y * sWe[1] + ea.z * sWe[2] + ea.w * sWe[3];
        r = r > 0.f ? r : 0.2f * r;
        float ev = expf(r);
        g_r[e] = ev;
        z += ev;
    }
#pragma unroll
    for (int off = 16; off; off >>= 1)
        z += __shfl_xor_sync(0xffffffffu, z, off);
    if ((threadIdx.x & 31) == 0) atomicAdd(&ssum, z);
    __syncthreads();
    if (threadIdx.x == 0) atomicAdd(&g_Z[zbase], ssum);
}

// ---------------- CSR edge aggregation (H=4, C=64), atomic-free ------------
__global__ void edgepass4_csr(const float* __restrict__ hbuf,
                              float* __restrict__ dst, int zbase) {
    int gw   = (blockIdx.x * blockDim.x + threadIdx.x) >> 5;
    int lane = threadIdx.x & 31;
    if (gw >= N_NODES) return;
    float4 Z = *(const float4*)(g_Z + zbase);
    float i0 = 0.25f / Z.x, i1 = 0.25f / Z.y, i2 = 0.25f / Z.z, i3 = 0.25f / Z.w;
    int b = g_off[gw], eEnd = g_off[gw + 1];
    float ax = 0.f, ay = 0.f;
#pragma unroll 4
    for (int i = b; i < eEnd; i++) {
        int s = __ldg(&g_csr_src[i]);
        int e = __ldg(&g_csr_eid[i]);
        float4 rv = __ldg((const float4*)g_r + e);
        const float2* hp = (const float2*)(hbuf + (size_t)s * 256);
        float2 v0 = __ldg(hp + lane);
        float2 v1 = __ldg(hp + 32 + lane);
        float2 v2 = __ldg(hp + 64 + lane);
        float2 v3 = __ldg(hp + 96 + lane);
        float a0 = rv.x * i0, a1 = rv.y * i1, a2 = rv.z * i2, a3 = rv.w * i3;
        ax += a0 * v0.x + a1 * v1.x + a2 * v2.x + a3 * v3.x;
        ay += a0 * v0.y + a1 * v1.y + a2 * v2.y + a3 * v3.y;
    }
    ((float2*)(dst + (size_t)gw * 64))[lane] = make_float2(ax, ay);
}

// ---------------- CSR edge aggregation (H=1, C=128) → d_out ----------------
__global__ void edgepass1_csr(const float* __restrict__ hbuf,
                              float* __restrict__ outp, int zbase) {
    int gw   = (blockIdx.x * blockDim.x + threadIdx.x) >> 5;
    int lane = threadIdx.x & 31;
    if (gw >= N_NODES) return;
    float iz = 1.0f / g_Z[zbase];
    int b = g_off[gw], eEnd = g_off[gw + 1];
    float x0 = 0.f, x1 = 0.f, x2 = 0.f, x3 = 0.f;
#pragma unroll 4
    for (int i = b; i < eEnd; i++) {
        int s = __ldg(&g_csr_src[i]);
        int e = __ldg(&g_csr_eid[i]);
        float a = __ldg(&g_r[e]) * iz;
        float4 v = __ldg((const float4*)(hbuf + (size_t)s * 128) + lane);
        x0 += a * v.x; x1 += a * v.y; x2 += a * v.z; x3 += a * v.w;
    }
    ((float4*)(outp + (size_t)gw * 128))[lane] = make_float4(x0, x1, x2, x3);
}

// ---------------- host -----------------------------------------------------
extern "C" void kernel_launch(void* const* d_in, const int* in_sizes, int n_in,
                              void* d_out, int out_size) {
    (void)in_sizes; (void)n_in; (void)out_size;
    const float* x     = (const float*)d_in[0];
    const int*   ei    = (const int*)  d_in[1];
    const float* eattr = (const float*)d_in[2];
    const int*   jt    = (const int*)  d_in[3];
    const float* emb   = (const float*)d_in[4];
    const float* W0    = (const float*)d_in[5];
    const float* as0   = (const float*)d_in[6];
    const float* ad0   = (const float*)d_in[7];
    const float* We0   = (const float*)d_in[8];
    const float* W1    = (const float*)d_in[9];
    const float* as1   = (const float*)d_in[10];
    const float* ad1   = (const float*)d_in[11];
    const float* We1   = (const float*)d_in[12];
    const float* W2    = (const float*)d_in[13];
    const float* as2   = (const float*)d_in[14];
    const float* ad2   = (const float*)d_in[15];
    const float* We2   = (const float*)d_in[16];
    float* out = (float*)d_out;

    float *p_feat0, *p_h, *p_accum;
    cudaGetSymbolAddress((void**)&p_feat0, g_feat0);
    cudaGetSymbolAddress((void**)&p_h,     g_h);
    cudaGetSymbolAddress((void**)&p_accum, g_accum);

    const int GEMM_BLOCKS = N_NODES / 25;                // 2000, exact
    const int EP_BLOCKS = (N_NODES * 32 + TB - 1) / TB;  // warp per node
    const int SW_BLOCKS = 2048;

    // CSR build + feature prep + p-vector precompute (3 launches)
    feat0hist_kernel<<<(W_P2 + TB - 1) / TB, TB>>>(x, jt, emb, ei,
                                                   W0, as0, ad0,
                                                   W1, as1, ad1,
                                                   W2, as2, ad2);
    scan_kernel<<<1, 1024>>>();
    scatter_kernel<<<(E_TOT + TB - 1) / TB, TB>>>(ei);

    // ---- layer 0 (H=4, C=64, IN=20) ----
    gemm_s4_kernel<IN0, 20, false, 0><<<GEMM_BLOCKS, 256>>>(p_feat0, W0, p_h);
    scoresum4_kernel<<<SW_BLOCKS, TB>>>(ei, eattr, We0, 0);
    edgepass4_csr<<<EP_BLOCKS, TB>>>(p_h, p_accum, 0);

    // ---- layer 1 (H=4, C=64, IN=64); ELU fused into gemm feature load ----
    gemm_s4_kernel<HID, 32, true, 80><<<GEMM_BLOCKS, 256>>>(p_accum, W1, p_h);
    scoresum4_kernel<<<SW_BLOCKS, TB>>>(ei, eattr, We1, 4);
    edgepass4_csr<<<EP_BLOCKS, TB>>>(p_h, p_accum, 4);

    // ---- layer 2 (H=1, C=128, IN=64); ELU fused; output -> d_out ----
    gemm_s1_kernel<HID, 64, true, 336><<<GEMM_BLOCKS, 128>>>(p_accum, W2, p_h);
    scoresum1_kernel<<<SW_BLOCKS, TB>>>(ei, eattr, We2, 8);
    edgepass1_csr<<<EP_BLOCKS, TB>>>(p_h, out, 8);
}

// round 12
// speedup vs baseline: 2.0904x; 1.1129x over previous
#include <cuda_runtime.h>
#include <cuda_fp16.h>
#include <cstdint>

// Problem dims (fixed by the dataset)
#define N_NODES 50000
#define N_EDGES 800000
#define E_TOT   850000   // + self loops
#define IN0     20
#define HID     64
#define OUTC    128
#define TB      256

// ---------------- scratch (device globals; no allocation allowed) ----------
__device__ __align__(16) float  g_feat0[N_NODES * IN0];   //  4.0 MB
__device__ __align__(16) __half g_hh[N_NODES * 256];      // 25.6 MB (h, fp16, per-layer scaled)
__device__ __align__(16) float  g_sA[N_NODES * 4];
__device__ __align__(16) float  g_sB[N_NODES * 4];
__device__ __align__(16) float  g_r[E_TOT * 4];           // 13.6 MB exp-values, CSR order
__device__ __align__(16) float  g_accum[N_NODES * HID];   // 12.8 MB (true scale, fp32)
__device__ __align__(16) float  g_Z[12];                  // L0:0-3  L1:4-7  L2:8
// precomputed score projection vectors  p[h,k] = sum_c W[h*C+c,k] * a[h,c]
__device__ float g_pA[400];
__device__ float g_pB[400];
// CSR by destination (identical for all 3 layers; rebuilt every launch)
__device__ int g_deg[N_NODES];        // static zero-init; re-zeroed by scan each launch
__device__ int g_off[N_NODES + 1];
__device__ int g_cur[N_NODES];
__device__ int g_csr_src[E_TOT];
__device__ int g_pos[E_TOT];          // edge id -> CSR slot (for CSR-ordered g_r writes)

// fp16 storage scale for layer l:
//   layer0: 256 (h0 ~ 0.5)
//   layer1: Z0 = g_Z[0]   (h1 ~ 1/Z0  since out0 ~ 1/Z0)
//   layer2: Z0*Z1 = g_Z[0]*g_Z[4]
// The edgepass divides by the same product, so correctness is exact; the
// scale only needs to keep h*S inside fp16 normal range (it does, ~1..1e3).

// ---------------- kernel 1: feat build + hist + Z reset + p-vectors --------
#define W_FEAT (N_NODES * IN0)
#define W_HIST (W_FEAT + N_EDGES)
#define W_LOOP (W_HIST + N_NODES)
#define W_Z    (W_LOOP + 12)
#define W_P0   (W_Z + 80)
#define W_P1   (W_P0 + 256)
#define W_P2   (W_P1 + 64)
__global__ void feat0hist_kernel(const float* __restrict__ x,
                                 const int*   __restrict__ jt,
                                 const float* __restrict__ emb,
                                 const int*   __restrict__ ei,
                                 const float* __restrict__ W0,
                                 const float* __restrict__ as0,
                                 const float* __restrict__ ad0,
                                 const float* __restrict__ W1,
                                 const float* __restrict__ as1,
                                 const float* __restrict__ ad1,
                                 const float* __restrict__ W2,
                                 const float* __restrict__ as2,
                                 const float* __restrict__ ad2) {
    int i = blockIdx.x * blockDim.x + threadIdx.x;
    if (i < W_FEAT) {
        int n = i / IN0, k = i - n * IN0;
        float v;
        if (k < 4) v = x[n * 4 + k];
        else       v = __ldg(&emb[jt[n] * 16 + (k - 4)]);
        g_feat0[i] = v;
    } else if (i < W_HIST) {
        int e = i - W_FEAT;
        atomicAdd(&g_deg[__ldg(&ei[N_EDGES + e])], 1);
    } else if (i < W_LOOP) {
        atomicAdd(&g_deg[i - W_HIST], 1);          // self loop per node
    } else if (i < W_Z) {
        g_Z[i - W_LOOP] = 0.f;
    } else if (i < W_P0) {                          // layer0 p-vectors
        int t = i - W_Z, h = t / IN0, k = t - h * IN0;
        float a = 0.f, b = 0.f;
        for (int c = 0; c < HID; c++) {
            float w = __ldg(&W0[(h * HID + c) * IN0 + k]);
            a += w * __ldg(&as0[h * HID + c]);
            b += w * __ldg(&ad0[h * HID + c]);
        }
        g_pA[t] = a; g_pB[t] = b;
    } else if (i < W_P1) {                          // layer1 p-vectors
        int t = i - W_P0, h = t >> 6, k = t & 63;
        float a = 0.f, b = 0.f;
        for (int c = 0; c < HID; c++) {
            float w = __ldg(&W1[(h * HID + c) * HID + k]);
            a += w * __ldg(&as1[h * HID + c]);
            b += w * __ldg(&ad1[h * HID + c]);
        }
        g_pA[80 + t] = a; g_pB[80 + t] = b;
    } else if (i < W_P2) {                          // layer2 p-vectors
        int k = i - W_P1;
        float a = 0.f, b = 0.f;
        for (int c = 0; c < OUTC; c++) {
            float w = __ldg(&W2[c * HID + k]);
            a += w * __ldg(&as2[c]);
            b += w * __ldg(&ad2[c]);
        }
        g_pA[336 + k] = a; g_pB[336 + k] = b;
    }
}

// ---------------- kernel 2: exclusive scan of degrees (1 block) ------------
__global__ void scan_kernel() {
    const int CH = (N_NODES + 1023) / 1024;        // 49
    __shared__ int ssum[1024];
    int t = threadIdx.x;
    int base = t * CH;
    int s = 0;
    for (int j = 0; j < CH; j++) {
        int idx = base + j;
        if (idx < N_NODES) s += g_deg[idx];
    }
    ssum[t] = s;
    __syncthreads();
    for (int off = 1; off < 1024; off <<= 1) {
        int v = (t >= off) ? ssum[t - off] : 0;
        __syncthreads();
        ssum[t] += v;
        __syncthreads();
    }
    int run = ssum[t] - s;
    for (int j = 0; j < CH; j++) {
        int idx = base + j;
        if (idx < N_NODES) {
            int d = g_deg[idx];
            g_off[idx] = run;
            g_cur[idx] = run;
            g_deg[idx] = 0;
            run += d;
        }
    }
    if (t == 1023) g_off[N_NODES] = ssum[1023];    // == E_TOT
}

// ---------------- kernel 3: CSR scatter (records edge->slot map) -----------
__global__ void scatter_kernel(const int* __restrict__ ei) {
    int e = blockIdx.x * blockDim.x + threadIdx.x;
    if (e >= E_TOT) return;
    int s, d;
    if (e < N_EDGES) { s = __ldg(&ei[e]); d = __ldg(&ei[N_EDGES + e]); }
    else             { s = d = e - N_EDGES; }
    int pos = atomicAdd(&g_cur[d], 1);
    g_csr_src[pos] = s;
    g_pos[e] = pos;
}

// ---------------- fused GEMM + attention scores (H=4, OUT=256) -------------
// blockDim=256, ROWS=25. W staged coalesced into smem -> regs.
// h stored fp16 (per-layer scale, see top) with [c][h]-interleaved rows so
// the edge pass reads each lane's 8 needed halves as ONE 16-byte load.
// SZ < 0: static scale 256; SZ >= 0: scale = g_Z[SZ].
template<int IN, int CH, bool ELU, int POFF, int SZ>
__global__ void gemm_s4_kernel(const float* __restrict__ feat,
                               const float* __restrict__ W,
                               __half* __restrict__ outh) {
    constexpr int ROWS = 25;
    constexpr int P = IN + 4;
    constexpr int NCHUNK = IN / CH;
    __shared__ __align__(16) float sW[256 * (CH + 1)];
    __shared__ __align__(16) float sfeat[ROWS * P];
    int t = threadIdx.x;
    int row0 = blockIdx.x * ROWS;
    for (int i = t; i < ROWS * IN; i += 256) {
        int row = i / IN, k = i - row * IN;
        float v = __ldg(&feat[row0 * IN + i]);
        if (ELU) v = v > 0.f ? v : expm1f(v);
        sfeat[row * P + k] = v;
    }
    float wreg[IN];
#pragma unroll
    for (int c = 0; c < NCHUNK; c++) {
        if (c) __syncthreads();
        for (int idx = t; idx < 256 * CH; idx += 256) {
            int row = idx / CH, kk = idx - row * CH;
            sW[row * (CH + 1) + kk] = __ldg(&W[row * IN + c * CH + kk]);
        }
        __syncthreads();
#pragma unroll
        for (int kk = 0; kk < CH; kk++)
            wreg[c * CH + kk] = sW[t * (CH + 1) + kk];
    }
    __syncthreads();
    float S = (SZ < 0) ? 256.0f : g_Z[SZ];
    int cc = t & 63, ht = t >> 6;                  // output column / head
#pragma unroll 5
    for (int r = 0; r < ROWS; r++) {
        const float4* sf4 = (const float4*)(sfeat + r * P);
        float acc0 = 0.f, acc1 = 0.f;
#pragma unroll
        for (int k4 = 0; k4 < IN / 4; k4++) {
            float4 f = sf4[k4];
            if (k4 & 1) {
                acc1 += wreg[4 * k4 + 0] * f.x;
                acc1 += wreg[4 * k4 + 1] * f.y;
                acc1 += wreg[4 * k4 + 2] * f.z;
                acc1 += wreg[4 * k4 + 3] * f.w;
            } else {
                acc0 += wreg[4 * k4 + 0] * f.x;
                acc0 += wreg[4 * k4 + 1] * f.y;
                acc0 += wreg[4 * k4 + 2] * f.z;
                acc0 += wreg[4 * k4 + 3] * f.w;
            }
        }
        outh[(size_t)(row0 + r) * 256 + cc * 4 + ht] =
            __float2half_rn((acc0 + acc1) * S);
    }
    // score tail: thread (r,h) computes sA/sB = sfeat[r,:] . p[h,:] (fp32, unscaled)
    if (t < ROWS * 4) {
        int r = t >> 2, h = t & 3;
        const float* fr = sfeat + r * P;
        float a0 = 0.f, a1 = 0.f, b0 = 0.f, b1 = 0.f;
#pragma unroll
        for (int k = 0; k < IN; k += 2) {
            float f0 = fr[k], f1 = fr[k + 1];
            a0 += f0 * __ldg(&g_pA[POFF + h * IN + k]);
            a1 += f1 * __ldg(&g_pA[POFF + h * IN + k + 1]);
            b0 += f0 * __ldg(&g_pB[POFF + h * IN + k]);
            b1 += f1 * __ldg(&g_pB[POFF + h * IN + k + 1]);
        }
        g_sA[(size_t)(row0 + r) * 4 + h] = a0 + a1;
        g_sB[(size_t)(row0 + r) * 4 + h] = b0 + b1;
    }
}

// ---------------- fused GEMM + scores (H=1, OUT=128), scale = Z0*Z1 --------
template<int IN, int CH, bool ELU, int POFF>
__global__ void gemm_s1_kernel(const float* __restrict__ feat,
                               const float* __restrict__ W,
                               __half* __restrict__ outh) {
    constexpr int ROWS = 25;
    constexpr int P = IN + 4;
    constexpr int NCHUNK = IN / CH;
    __shared__ __align__(16) float sW[128 * (CH + 1)];
    __shared__ __align__(16) float sfeat[ROWS * P];
    int t = threadIdx.x;
    int row0 = blockIdx.x * ROWS;
    for (int i = t; i < ROWS * IN; i += 128) {
        int row = i / IN, k = i - row * IN;
        float v = __ldg(&feat[row0 * IN + i]);
        if (ELU) v = v > 0.f ? v : expm1f(v);
        sfeat[row * P + k] = v;
    }
    float wreg[IN];
#pragma unroll
    for (int c = 0; c < NCHUNK; c++) {
        if (c) __syncthreads();
        for (int idx = t; idx < 128 * CH; idx += 128) {
            int row = idx / CH, kk = idx - row * CH;
            sW[row * (CH + 1) + kk] = __ldg(&W[row * IN + c * CH + kk]);
        }
        __syncthreads();
#pragma unroll
        for (int kk = 0; kk < CH; kk++)
            wreg[c * CH + kk] = sW[t * (CH + 1) + kk];
    }
    __syncthreads();
    float S = g_Z[0] * g_Z[4];                     // Z0 * Z1
#pragma unroll 5
    for (int r = 0; r < ROWS; r++) {
        const float4* sf4 = (const float4*)(sfeat + r * P);
        float acc0 = 0.f, acc1 = 0.f;
#pragma unroll
        for (int k4 = 0; k4 < IN / 4; k4++) {
            float4 f = sf4[k4];
            if (k4 & 1) {
                acc1 += wreg[4 * k4 + 0] * f.x;
                acc1 += wreg[4 * k4 + 1] * f.y;
                acc1 += wreg[4 * k4 + 2] * f.z;
                acc1 += wreg[4 * k4 + 3] * f.w;
            } else {
                acc0 += wreg[4 * k4 + 0] * f.x;
                acc0 += wreg[4 * k4 + 1] * f.y;
                acc0 += wreg[4 * k4 + 2] * f.z;
                acc0 += wreg[4 * k4 + 3] * f.w;
            }
        }
        outh[(size_t)(row0 + r) * 128 + t] =
            __float2half_rn((acc0 + acc1) * S);
    }
    if (t < ROWS) {
        const float* fr = sfeat + t * P;
        float a0 = 0.f, a1 = 0.f, b0 = 0.f, b1 = 0.f;
#pragma unroll
        for (int k = 0; k < IN; k += 2) {
            float f0 = fr[k], f1 = fr[k + 1];
            a0 += f0 * __ldg(&g_pA[POFF + k]);
            a1 += f1 * __ldg(&g_pA[POFF + k + 1]);
            b0 += f0 * __ldg(&g_pB[POFF + k]);
            b1 += f1 * __ldg(&g_pB[POFF + k + 1]);
        }
        g_sA[row0 + t] = a0 + a1;
        g_sB[row0 + t] = b0 + b1;
    }
}

// ---------------- fused edge scores + exp + Z-sum (H = 4) ------------------
// Writes exp values in CSR slot order (g_pos) so the edge pass reads
// sequentially with no eid indirection.
__global__ void scoresum4_kernel(const int* __restrict__ ei,
                                 const float* __restrict__ eattr,
                                 const float* __restrict__ We,
                                 int zbase) {
    __shared__ float sWe[16];
    __shared__ float ssum[4];
    if (threadIdx.x < 16) sWe[threadIdx.x] = We[threadIdx.x];
    if (threadIdx.x < 4)  ssum[threadIdx.x] = 0.f;
    __syncthreads();
    float z0 = 0.f, z1 = 0.f, z2 = 0.f, z3 = 0.f;
    int stride = gridDim.x * blockDim.x;
    for (int e = blockIdx.x * blockDim.x + threadIdx.x; e < E_TOT; e += stride) {
        int s, d; float4 ea;
        if (e < N_EDGES) {
            s = __ldg(&ei[e]); d = __ldg(&ei[N_EDGES + e]);
            ea = __ldg((const float4*)eattr + e);
        } else {
            s = d = e - N_EDGES; ea = make_float4(0.f, 0.f, 0.f, 0.f);
        }
        float4 va = __ldg((const float4*)g_sA + d);
        float4 vb = __ldg((const float4*)g_sB + s);
        float r0 = va.x + vb.x + ea.x * sWe[0]  + ea.y * sWe[1]  + ea.z * sWe[2]  + ea.w * sWe[3];
        float r1 = va.y + vb.y + ea.x * sWe[4]  + ea.y * sWe[5]  + ea.z * sWe[6]  + ea.w * sWe[7];
        float r2 = va.z + vb.z + ea.x * sWe[8]  + ea.y * sWe[9]  + ea.z * sWe[10] + ea.w * sWe[11];
        float r3 = va.w + vb.w + ea.x * sWe[12] + ea.y * sWe[13] + ea.z * sWe[14] + ea.w * sWe[15];
        r0 = r0 > 0.f ? r0 : 0.2f * r0;
        r1 = r1 > 0.f ? r1 : 0.2f * r1;
        r2 = r2 > 0.f ? r2 : 0.2f * r2;
        r3 = r3 > 0.f ? r3 : 0.2f * r3;
        float e0 = expf(r0), e1 = expf(r1), e2 = expf(r2), e3 = expf(r3);
        ((float4*)g_r)[__ldg(&g_pos[e])] = make_float4(e0, e1, e2, e3);
        z0 += e0; z1 += e1; z2 += e2; z3 += e3;
    }
#pragma unroll
    for (int off = 16; off; off >>= 1) {
        z0 += __shfl_xor_sync(0xffffffffu, z0, off);
        z1 += __shfl_xor_sync(0xffffffffu, z1, off);
        z2 += __shfl_xor_sync(0xffffffffu, z2, off);
        z3 += __shfl_xor_sync(0xffffffffu, z3, off);
    }
    if ((threadIdx.x & 31) == 0) {
        atomicAdd(&ssum[0], z0); atomicAdd(&ssum[1], z1);
        atomicAdd(&ssum[2], z2); atomicAdd(&ssum[3], z3);
    }
    __syncthreads();
    if (threadIdx.x < 4) atomicAdd(&g_Z[zbase + threadIdx.x], ssum[threadIdx.x]);
}

// ---------------- fused edge scores + exp + Z-sum (H = 1) ------------------
__global__ void scoresum1_kernel(const int* __restrict__ ei,
                                 const float* __restrict__ eattr,
                                 const float* __restrict__ We,
                                 int zbase) {
    __shared__ float sWe[4];
    __shared__ float ssum;
    if (threadIdx.x < 4)  sWe[threadIdx.x] = We[threadIdx.x];
    if (threadIdx.x == 0) ssum = 0.f;
    __syncthreads();
    float z = 0.f;
    int stride = gridDim.x * blockDim.x;
    for (int e = blockIdx.x * blockDim.x + threadIdx.x; e < E_TOT; e += stride) {
        int s, d; float4 ea;
        if (e < N_EDGES) {
            s = __ldg(&ei[e]); d = __ldg(&ei[N_EDGES + e]);
            ea = __ldg((const float4*)eattr + e);
        } else {
            s = d = e - N_EDGES; ea = make_float4(0.f, 0.f, 0.f, 0.f);
        }
        float r = __ldg(&g_sA[d]) + __ldg(&g_sB[s])
                + ea.x * sWe[0] + ea.y * sWe[1] + ea.z * sWe[2] + ea.w * sWe[3];
        r = r > 0.f ? r : 0.2f * r;
        float ev = expf(r);
        g_r[__ldg(&g_pos[e])] = ev;
        z += ev;
    }
#pragma unroll
    for (int off = 16; off; off >>= 1)
        z += __shfl_xor_sync(0xffffffffu, z, off);
    if ((threadIdx.x & 31) == 0) atomicAdd(&ssum, z);
    __syncthreads();
    if (threadIdx.x == 0) atomicAdd(&g_Z[zbase], ssum);
}

// ---------------- CSR edge aggregation (H=4, C=64), fp16 gather ------------
// Warp per dst node; lane reads ONE 16B chunk = 8 halves = 2 cols x 4 heads.
// SZ < 0: h scale 256; SZ >= 0: h scale g_Z[SZ].
template<int SZ>
__global__ void edgepass4_csr(const __half* __restrict__ hbuf,
                              float* __restrict__ dst, int zbase) {
    int gw   = (blockIdx.x * blockDim.x + threadIdx.x) >> 5;
    int lane = threadIdx.x & 31;
    if (gw >= N_NODES) return;
    float S = (SZ < 0) ? 256.0f : g_Z[SZ];
    float4 Z = *(const float4*)(g_Z + zbase);
    const float isc = 0.25f / S;
    float i0 = isc / Z.x, i1 = isc / Z.y, i2 = isc / Z.z, i3 = isc / Z.w;
    int b = g_off[gw], eEnd = g_off[gw + 1];
    float ax = 0.f, ay = 0.f;
#pragma unroll 4
    for (int i = b; i < eEnd; i++) {
        int s = __ldg(&g_csr_src[i]);
        float4 rv = __ldg((const float4*)g_r + i);
        uint4 v = __ldg((const uint4*)(hbuf + (size_t)s * 256) + lane);
        float a0 = rv.x * i0, a1 = rv.y * i1, a2 = rv.z * i2, a3 = rv.w * i3;
        float2 c0a = __half22float2(*(const __half2*)&v.x);  // c0: h0,h1
        float2 c0b = __half22float2(*(const __half2*)&v.y);  // c0: h2,h3
        float2 c1a = __half22float2(*(const __half2*)&v.z);  // c1: h0,h1
        float2 c1b = __half22float2(*(const __half2*)&v.w);  // c1: h2,h3
        ax += a0 * c0a.x + a1 * c0a.y + a2 * c0b.x + a3 * c0b.y;
        ay += a0 * c1a.x + a1 * c1a.y + a2 * c1b.x + a3 * c1b.y;
    }
    ((float2*)(dst + (size_t)gw * 64))[lane] = make_float2(ax, ay);
}

// ---------------- CSR edge aggregation (H=1, C=128) → d_out ----------------
__global__ void edgepass1_csr(const __half* __restrict__ hbuf,
                              float* __restrict__ outp) {
    int gw   = (blockIdx.x * blockDim.x + threadIdx.x) >> 5;
    int lane = threadIdx.x & 31;
    if (gw >= N_NODES) return;
    float iz = 1.0f / (g_Z[0] * g_Z[4] * g_Z[8]);  // undo scale Z0*Z1, divide by Z2
    int b = g_off[gw], eEnd = g_off[gw + 1];
    float x0 = 0.f, x1 = 0.f, x2 = 0.f, x3 = 0.f;
#pragma unroll 4
    for (int i = b; i < eEnd; i++) {
        int s = __ldg(&g_csr_src[i]);
        float a = __ldg(&g_r[i]) * iz;
        uint2 v = __ldg((const uint2*)(hbuf + (size_t)s * 128) + lane);
        float2 q0 = __half22float2(*(const __half2*)&v.x);
        float2 q1 = __half22float2(*(const __half2*)&v.y);
        x0 += a * q0.x; x1 += a * q0.y; x2 += a * q1.x; x3 += a * q1.y;
    }
    ((float4*)(outp + (size_t)gw * 128))[lane] = make_float4(x0, x1, x2, x3);
}

// ---------------- host -----------------------------------------------------
extern "C" void kernel_launch(void* const* d_in, const int* in_sizes, int n_in,
                              void* d_out, int out_size) {
    (void)in_sizes; (void)n_in; (void)out_size;
    const float* x     = (const float*)d_in[0];
    const int*   ei    = (const int*)  d_in[1];
    const float* eattr = (const float*)d_in[2];
    const int*   jt    = (const int*)  d_in[3];
    const float* emb   = (const float*)d_in[4];
    const float* W0    = (const float*)d_in[5];
    const float* as0   = (const float*)d_in[6];
    const float* ad0   = (const float*)d_in[7];
    const float* We0   = (const float*)d_in[8];
    const float* W1    = (const float*)d_in[9];
    const float* as1   = (const float*)d_in[10];
    const float* ad1   = (const float*)d_in[11];
    const float* We1   = (const float*)d_in[12];
    const float* W2    = (const float*)d_in[13];
    const float* as2   = (const float*)d_in[14];
    const float* ad2   = (const float*)d_in[15];
    const float* We2   = (const float*)d_in[16];
    float* out = (float*)d_out;

    float *p_feat0, *p_accum;
    __half *p_hh;
    cudaGetSymbolAddress((void**)&p_feat0, g_feat0);
    cudaGetSymbolAddress((void**)&p_hh,    g_hh);
    cudaGetSymbolAddress((void**)&p_accum, g_accum);

    const int GEMM_BLOCKS = N_NODES / 25;                // 2000, exact
    const int EP_BLOCKS = (N_NODES * 32 + TB - 1) / TB;  // warp per node
    const int SW_BLOCKS = 2048;

    // CSR build + feature prep + p-vector precompute (3 launches)
    feat0hist_kernel<<<(W_P2 + TB - 1) / TB, TB>>>(x, jt, emb, ei,
                                                   W0, as0, ad0,
                                                   W1, as1, ad1,
                                                   W2, as2, ad2);
    scan_kernel<<<1, 1024>>>();
    scatter_kernel<<<(E_TOT + TB - 1) / TB, TB>>>(ei);

    // ---- layer 0 (H=4, C=64, IN=20); h scale 256 ----
    gemm_s4_kernel<IN0, 20, false, 0, -1><<<GEMM_BLOCKS, 256>>>(p_feat0, W0, p_hh);
    scoresum4_kernel<<<SW_BLOCKS, TB>>>(ei, eattr, We0, 0);
    edgepass4_csr<-1><<<EP_BLOCKS, TB>>>(p_hh, p_accum, 0);

    // ---- layer 1 (H=4, C=64, IN=64); ELU fused; h scale Z0 ----
    gemm_s4_kernel<HID, 32, true, 80, 0><<<GEMM_BLOCKS, 256>>>(p_accum, W1, p_hh);
    scoresum4_kernel<<<SW_BLOCKS, TB>>>(ei, eattr, We1, 4);
    edgepass4_csr<0><<<EP_BLOCKS, TB>>>(p_hh, p_accum, 4);

    // ---- layer 2 (H=1, C=128, IN=64); ELU fused; h scale Z0*Z1; -> d_out --
    gemm_s1_kernel<HID, 64, true, 336><<<GEMM_BLOCKS, 128>>>(p_accum, W2, p_hh);
    scoresum1_kernel<<<SW_BLOCKS, TB>>>(ei, eattr, We2, 8);
    edgepass1_csr<<<EP_BLOCKS, TB>>>(p_hh, out);
}

// round 14
// speedup vs baseline: 2.1696x; 1.0379x over previous
#include <cuda_runtime.h>
#include <cuda_fp16.h>
#include <cstdint>

// Problem dims (fixed by the dataset)
#define N_NODES 50000
#define N_EDGES 800000
#define E_TOT   850000   // + self loops
#define IN0     20
#define HID     64
#define OUTC    128
#define TB      256

// ---------------- scratch (device globals; no allocation allowed) ----------
__device__ __align__(16) float  g_feat0[N_NODES * IN0];   //  4.0 MB
__device__ __align__(16) __half g_hh[N_NODES * 256];      // 25.6 MB (h, fp16, per-layer scaled)
__device__ __align__(16) float  g_sA[N_NODES * 4];
__device__ __align__(16) float  g_sB[N_NODES * 4];
__device__ __align__(16) float  g_r[E_TOT * 4];           // 13.6 MB exp-values, CSR order
__device__ __align__(16) float  g_accum[N_NODES * HID];   // 12.8 MB (true scale, fp32)
__device__ __align__(16) float  g_Z[12];                  // L0:0-3  L1:4-7  L2:8
// precomputed score projection vectors  p[h,k] = sum_c W[h*C+c,k] * a[h,c]
__device__ float g_pA[400];
__device__ float g_pB[400];
// CSR by destination (identical for all 3 layers; rebuilt every launch)
__device__ int g_deg[N_NODES];        // static zero-init; re-zeroed by scan each launch
__device__ int g_off[N_NODES + 1];
__device__ int g_cur[N_NODES];
__device__ int g_csr_src[E_TOT];
__device__ int g_pos[E_TOT];          // edge id -> CSR slot (for CSR-ordered g_r writes)

// fp16 storage scale for layer l:
//   layer0: 256 (h0 ~ 0.5)
//   layer1: Z0 = g_Z[0]   (h1 ~ 1/Z0  since out0 ~ 1/Z0)
//   layer2: Z0*Z1 = g_Z[0]*g_Z[4]
// The edgepass divides by the same product, so correctness is exact; the
// scale only needs to keep h*S inside fp16 normal range (it does, ~1..1e3).

// ---------------- kernel 1: feat build + hist + Z reset + p-vectors --------
#define W_FEAT (N_NODES * IN0)
#define W_HIST (W_FEAT + N_EDGES)
#define W_LOOP (W_HIST + N_NODES)
#define W_Z    (W_LOOP + 12)
#define W_P0   (W_Z + 80)
#define W_P1   (W_P0 + 256)
#define W_P2   (W_P1 + 64)
__global__ void feat0hist_kernel(const float* __restrict__ x,
                                 const int*   __restrict__ jt,
                                 const float* __restrict__ emb,
                                 const int*   __restrict__ ei,
                                 const float* __restrict__ W0,
                                 const float* __restrict__ as0,
                                 const float* __restrict__ ad0,
                                 const float* __restrict__ W1,
                                 const float* __restrict__ as1,
                                 const float* __restrict__ ad1,
                                 const float* __restrict__ W2,
                                 const float* __restrict__ as2,
                                 const float* __restrict__ ad2) {
    int i = blockIdx.x * blockDim.x + threadIdx.x;
    if (i < W_FEAT) {
        int n = i / IN0, k = i - n * IN0;
        float v;
        if (k < 4) v = x[n * 4 + k];
        else       v = __ldg(&emb[jt[n] * 16 + (k - 4)]);
        g_feat0[i] = v;
    } else if (i < W_HIST) {
        int e = i - W_FEAT;
        atomicAdd(&g_deg[__ldg(&ei[N_EDGES + e])], 1);
    } else if (i < W_LOOP) {
        atomicAdd(&g_deg[i - W_HIST], 1);          // self loop per node
    } else if (i < W_Z) {
        g_Z[i - W_LOOP] = 0.f;
    } else if (i < W_P0) {                          // layer0 p-vectors
        int t = i - W_Z, h = t / IN0, k = t - h * IN0;
        float a = 0.f, b = 0.f;
        for (int c = 0; c < HID; c++) {
            float w = __ldg(&W0[(h * HID + c) * IN0 + k]);
            a += w * __ldg(&as0[h * HID + c]);
            b += w * __ldg(&ad0[h * HID + c]);
        }
        g_pA[t] = a; g_pB[t] = b;
    } else if (i < W_P1) {                          // layer1 p-vectors
        int t = i - W_P0, h = t >> 6, k = t & 63;
        float a = 0.f, b = 0.f;
        for (int c = 0; c < HID; c++) {
            float w = __ldg(&W1[(h * HID + c) * HID + k]);
            a += w * __ldg(&as1[h * HID + c]);
            b += w * __ldg(&ad1[h * HID + c]);
        }
        g_pA[80 + t] = a; g_pB[80 + t] = b;
    } else if (i < W_P2) {                          // layer2 p-vectors
        int k = i - W_P1;
        float a = 0.f, b = 0.f;
        for (int c = 0; c < OUTC; c++) {
            float w = __ldg(&W2[c * HID + k]);
            a += w * __ldg(&as2[c]);
            b += w * __ldg(&ad2[c]);
        }
        g_pA[336 + k] = a; g_pB[336 + k] = b;
    }
}

// ---------------- kernel 2: exclusive scan of degrees (1 block) ------------
__global__ void scan_kernel() {
    const int CH = (N_NODES + 1023) / 1024;        // 49
    __shared__ int ssum[1024];
    int t = threadIdx.x;
    int base = t * CH;
    int s = 0;
    for (int j = 0; j < CH; j++) {
        int idx = base + j;
        if (idx < N_NODES) s += g_deg[idx];
    }
    ssum[t] = s;
    __syncthreads();
    for (int off = 1; off < 1024; off <<= 1) {
        int v = (t >= off) ? ssum[t - off] : 0;
        __syncthreads();
        ssum[t] += v;
        __syncthreads();
    }
    int run = ssum[t] - s;
    for (int j = 0; j < CH; j++) {
        int idx = base + j;
        if (idx < N_NODES) {
            int d = g_deg[idx];
            g_off[idx] = run;
            g_cur[idx] = run;
            g_deg[idx] = 0;
            run += d;
        }
    }
    if (t == 1023) g_off[N_NODES] = ssum[1023];    // == E_TOT
}

// ---------------- kernel 3: CSR scatter (records edge->slot map) -----------
__global__ void scatter_kernel(const int* __restrict__ ei) {
    int e = blockIdx.x * blockDim.x + threadIdx.x;
    if (e >= E_TOT) return;
    int s, d;
    if (e < N_EDGES) { s = __ldg(&ei[e]); d = __ldg(&ei[N_EDGES + e]); }
    else             { s = d = e - N_EDGES; }
    int pos = atomicAdd(&g_cur[d], 1);
    g_csr_src[pos] = s;
    g_pos[e] = pos;
}

// ---------------- fused GEMM + attention scores (H=4, OUT=256) -------------
// blockDim=256, ROWS=25. W staged coalesced into smem -> regs.
// h stored fp16 (per-layer scale, see top) with [c][h]-interleaved rows so
// the edge pass reads each lane's 8 needed halves as ONE 16-byte load.
// SZ < 0: static scale 256; SZ >= 0: scale = g_Z[SZ].
template<int IN, int CH, bool ELU, int POFF, int SZ>
__global__ void gemm_s4_kernel(const float* __restrict__ feat,
                               const float* __restrict__ W,
                               __half* __restrict__ outh) {
    constexpr int ROWS = 25;
    constexpr int P = IN + 4;
    constexpr int NCHUNK = IN / CH;
    __shared__ __align__(16) float sW[256 * (CH + 1)];
    __shared__ __align__(16) float sfeat[ROWS * P];
    int t = threadIdx.x;
    int row0 = blockIdx.x * ROWS;
    for (int i = t; i < ROWS * IN; i += 256) {
        int row = i / IN, k = i - row * IN;
        float v = __ldg(&feat[row0 * IN + i]);
        if (ELU) v = v > 0.f ? v : expm1f(v);
        sfeat[row * P + k] = v;
    }
    float wreg[IN];
#pragma unroll
    for (int c = 0; c < NCHUNK; c++) {
        if (c) __syncthreads();
        for (int idx = t; idx < 256 * CH; idx += 256) {
            int row = idx / CH, kk = idx - row * CH;
            sW[row * (CH + 1) + kk] = __ldg(&W[row * IN + c * CH + kk]);
        }
        __syncthreads();
#pragma unroll
        for (int kk = 0; kk < CH; kk++)
            wreg[c * CH + kk] = sW[t * (CH + 1) + kk];
    }
    __syncthreads();
    float S = (SZ < 0) ? 256.0f : g_Z[SZ];
    int cc = t & 63, ht = t >> 6;                  // output column / head
#pragma unroll 5
    for (int r = 0; r < ROWS; r++) {
        const float4* sf4 = (const float4*)(sfeat + r * P);
        float acc0 = 0.f, acc1 = 0.f;
#pragma unroll
        for (int k4 = 0; k4 < IN / 4; k4++) {
            float4 f = sf4[k4];
            if (k4 & 1) {
                acc1 += wreg[4 * k4 + 0] * f.x;
                acc1 += wreg[4 * k4 + 1] * f.y;
                acc1 += wreg[4 * k4 + 2] * f.z;
                acc1 += wreg[4 * k4 + 3] * f.w;
            } else {
                acc0 += wreg[4 * k4 + 0] * f.x;
                acc0 += wreg[4 * k4 + 1] * f.y;
                acc0 += wreg[4 * k4 + 2] * f.z;
                acc0 += wreg[4 * k4 + 3] * f.w;
            }
        }
        outh[(size_t)(row0 + r) * 256 + cc * 4 + ht] =
            __float2half_rn((acc0 + acc1) * S);
    }
    // score tail: thread (r,h) computes sA/sB = sfeat[r,:] . p[h,:] (fp32, unscaled)
    if (t < ROWS * 4) {
        int r = t >> 2, h = t & 3;
        const float* fr = sfeat + r * P;
        float a0 = 0.f, a1 = 0.f, b0 = 0.f, b1 = 0.f;
#pragma unroll
        for (int k = 0; k < IN; k += 2) {
            float f0 = fr[k], f1 = fr[k + 1];
            a0 += f0 * __ldg(&g_pA[POFF + h * IN + k]);
            a1 += f1 * __ldg(&g_pA[POFF + h * IN + k + 1]);
            b0 += f0 * __ldg(&g_pB[POFF + h * IN + k]);
            b1 += f1 * __ldg(&g_pB[POFF + h * IN + k + 1]);
        }
        g_sA[(size_t)(row0 + r) * 4 + h] = a0 + a1;
        g_sB[(size_t)(row0 + r) * 4 + h] = b0 + b1;
    }
}

// ---------------- fused GEMM + scores (H=1, OUT=128), scale = Z0*Z1 --------
template<int IN, int CH, bool ELU, int POFF>
__global__ void gemm_s1_kernel(const float* __restrict__ feat,
                               const float* __restrict__ W,
                               __half* __restrict__ outh) {
    constexpr int ROWS = 25;
    constexpr int P = IN + 4;
    constexpr int NCHUNK = IN / CH;
    __shared__ __align__(16) float sW[128 * (CH + 1)];
    __shared__ __align__(16) float sfeat[ROWS * P];
    int t = threadIdx.x;
    int row0 = blockIdx.x * ROWS;
    for (int i = t; i < ROWS * IN; i += 128) {
        int row = i / IN, k = i - row * IN;
        float v = __ldg(&feat[row0 * IN + i]);
        if (ELU) v = v > 0.f ? v : expm1f(v);
        sfeat[row * P + k] = v;
    }
    float wreg[IN];
#pragma unroll
    for (int c = 0; c < NCHUNK; c++) {
        if (c) __syncthreads();
        for (int idx = t; idx < 128 * CH; idx += 128) {
            int row = idx / CH, kk = idx - row * CH;
            sW[row * (CH + 1) + kk] = __ldg(&W[row * IN + c * CH + kk]);
        }
        __syncthreads();
#pragma unroll
        for (int kk = 0; kk < CH; kk++)
            wreg[c * CH + kk] = sW[t * (CH + 1) + kk];
    }
    __syncthreads();
    float S = g_Z[0] * g_Z[4];                     // Z0 * Z1
#pragma unroll 5
    for (int r = 0; r < ROWS; r++) {
        const float4* sf4 = (const float4*)(sfeat + r * P);
        float acc0 = 0.f, acc1 = 0.f;
#pragma unroll
        for (int k4 = 0; k4 < IN / 4; k4++) {
            float4 f = sf4[k4];
            if (k4 & 1) {
                acc1 += wreg[4 * k4 + 0] * f.x;
                acc1 += wreg[4 * k4 + 1] * f.y;
                acc1 += wreg[4 * k4 + 2] * f.z;
                acc1 += wreg[4 * k4 + 3] * f.w;
            } else {
                acc0 += wreg[4 * k4 + 0] * f.x;
                acc0 += wreg[4 * k4 + 1] * f.y;
                acc0 += wreg[4 * k4 + 2] * f.z;
                acc0 += wreg[4 * k4 + 3] * f.w;
            }
        }
        outh[(size_t)(row0 + r) * 128 + t] =
            __float2half_rn((acc0 + acc1) * S);
    }
    if (t < ROWS) {
        const float* fr = sfeat + t * P;
        float a0 = 0.f, a1 = 0.f, b0 = 0.f, b1 = 0.f;
#pragma unroll
        for (int k = 0; k < IN; k += 2) {
            float f0 = fr[k], f1 = fr[k + 1];
            a0 += f0 * __ldg(&g_pA[POFF + k]);
            a1 += f1 * __ldg(&g_pA[POFF + k + 1]);
            b0 += f0 * __ldg(&g_pB[POFF + k]);
            b1 += f1 * __ldg(&g_pB[POFF + k + 1]);
        }
        g_sA[row0 + t] = a0 + a1;
        g_sB[row0 + t] = b0 + b1;
    }
}

// ---------------- fused edge scores + exp + Z-sum (H = 4) ------------------
// Writes exp values in CSR slot order (g_pos) so the edge pass reads
// sequentially with no eid indirection.  __expf = MUFU.EX2 path.
__global__ void scoresum4_kernel(const int* __restrict__ ei,
                                 const float* __restrict__ eattr,
                                 const float* __restrict__ We,
                                 int zbase) {
    __shared__ float sWe[16];
    __shared__ float ssum[4];
    if (threadIdx.x < 16) sWe[threadIdx.x] = We[threadIdx.x];
    if (threadIdx.x < 4)  ssum[threadIdx.x] = 0.f;
    __syncthreads();
    float z0 = 0.f, z1 = 0.f, z2 = 0.f, z3 = 0.f;
    int stride = gridDim.x * blockDim.x;
    for (int e = blockIdx.x * blockDim.x + threadIdx.x; e < E_TOT; e += stride) {
        int s, d; float4 ea;
        if (e < N_EDGES) {
            s = __ldg(&ei[e]); d = __ldg(&ei[N_EDGES + e]);
            ea = __ldg((const float4*)eattr + e);
        } else {
            s = d = e - N_EDGES; ea = make_float4(0.f, 0.f, 0.f, 0.f);
        }
        float4 va = __ldg((const float4*)g_sA + d);
        float4 vb = __ldg((const float4*)g_sB + s);
        float r0 = va.x + vb.x + ea.x * sWe[0]  + ea.y * sWe[1]  + ea.z * sWe[2]  + ea.w * sWe[3];
        float r1 = va.y + vb.y + ea.x * sWe[4]  + ea.y * sWe[5]  + ea.z * sWe[6]  + ea.w * sWe[7];
        float r2 = va.z + vb.z + ea.x * sWe[8]  + ea.y * sWe[9]  + ea.z * sWe[10] + ea.w * sWe[11];
        float r3 = va.w + vb.w + ea.x * sWe[12] + ea.y * sWe[13] + ea.z * sWe[14] + ea.w * sWe[15];
        r0 = r0 > 0.f ? r0 : 0.2f * r0;
        r1 = r1 > 0.f ? r1 : 0.2f * r1;
        r2 = r2 > 0.f ? r2 : 0.2f * r2;
        r3 = r3 > 0.f ? r3 : 0.2f * r3;
        float e0 = __expf(r0), e1 = __expf(r1), e2 = __expf(r2), e3 = __expf(r3);
        ((float4*)g_r)[__ldg(&g_pos[e])] = make_float4(e0, e1, e2, e3);
        z0 += e0; z1 += e1; z2 += e2; z3 += e3;
    }
#pragma unroll
    for (int off = 16; off; off >>= 1) {
        z0 += __shfl_xor_sync(0xffffffffu, z0, off);
        z1 += __shfl_xor_sync(0xffffffffu, z1, off);
        z2 += __shfl_xor_sync(0xffffffffu, z2, off);
        z3 += __shfl_xor_sync(0xffffffffu, z3, off);
    }
    if ((threadIdx.x & 31) == 0) {
        atomicAdd(&ssum[0], z0); atomicAdd(&ssum[1], z1);
        atomicAdd(&ssum[2], z2); atomicAdd(&ssum[3], z3);
    }
    __syncthreads();
    if (threadIdx.x < 4) atomicAdd(&g_Z[zbase + threadIdx.x], ssum[threadIdx.x]);
}

// ---------------- fused edge scores + exp + Z-sum (H = 1) ------------------
__global__ void scoresum1_kernel(const int* __restrict__ ei,
                                 const float* __restrict__ eattr,
                                 const float* __restrict__ We,
                                 int zbase) {
    __shared__ float sWe[4];
    __shared__ float ssum;
    if (threadIdx.x < 4)  sWe[threadIdx.x] = We[threadIdx.x];
    if (threadIdx.x == 0) ssum = 0.f;
    __syncthreads();
    float z = 0.f;
    int stride = gridDim.x * blockDim.x;
    for (int e = blockIdx.x * blockDim.x + threadIdx.x; e < E_TOT; e += stride) {
        int s, d; float4 ea;
        if (e < N_EDGES) {
            s = __ldg(&ei[e]); d = __ldg(&ei[N_EDGES + e]);
            ea = __ldg((const float4*)eattr + e);
        } else {
            s = d = e - N_EDGES; ea = make_float4(0.f, 0.f, 0.f, 0.f);
        }
        float r = __ldg(&g_sA[d]) + __ldg(&g_sB[s])
                + ea.x * sWe[0] + ea.y * sWe[1] + ea.z * sWe[2] + ea.w * sWe[3];
        r = r > 0.f ? r : 0.2f * r;
        float ev = __expf(r);
        g_r[__ldg(&g_pos[e])] = ev;
        z += ev;
    }
#pragma unroll
    for (int off = 16; off; off >>= 1)
        z += __shfl_xor_sync(0xffffffffu, z, off);
    if ((threadIdx.x & 31) == 0) atomicAdd(&ssum, z);
    __syncthreads();
    if (threadIdx.x == 0) atomicAdd(&g_Z[zbase], ssum);
}

// ---------------- CSR edge aggregation (H=4, C=64), fp16 gather ------------
// Warp per dst node; lane reads ONE 16B chunk = 8 halves = 2 cols x 4 heads.
// SZ < 0: h scale 256; SZ >= 0: h scale g_Z[SZ].
template<int SZ>
__global__ void edgepass4_csr(const __half* __restrict__ hbuf,
                              float* __restrict__ dst, int zbase) {
    int gw   = (blockIdx.x * blockDim.x + threadIdx.x) >> 5;
    int lane = threadIdx.x & 31;
    if (gw >= N_NODES) return;
    float S = (SZ < 0) ? 256.0f : g_Z[SZ];
    float4 Z = *(const float4*)(g_Z + zbase);
    const float isc = 0.25f / S;
    float i0 = isc / Z.x, i1 = isc / Z.y, i2 = isc / Z.z, i3 = isc / Z.w;
    int b = g_off[gw], eEnd = g_off[gw + 1];
    float ax = 0.f, ay = 0.f;
#pragma unroll 4
    for (int i = b; i < eEnd; i++) {
        int s = __ldg(&g_csr_src[i]);
        float4 rv = __ldg((const float4*)g_r + i);
        uint4 v = __ldg((const uint4*)(hbuf + (size_t)s * 256) + lane);
        float a0 = rv.x * i0, a1 = rv.y * i1, a2 = rv.z * i2, a3 = rv.w * i3;
        float2 c0a = __half22float2(*(const __half2*)&v.x);  // c0: h0,h1
        float2 c0b = __half22float2(*(const __half2*)&v.y);  // c0: h2,h3
        float2 c1a = __half22float2(*(const __half2*)&v.z);  // c1: h0,h1
        float2 c1b = __half22float2(*(const __half2*)&v.w);  // c1: h2,h3
        ax += a0 * c0a.x + a1 * c0a.y + a2 * c0b.x + a3 * c0b.y;
        ay += a0 * c1a.x + a1 * c1a.y + a2 * c1b.x + a3 * c1b.y;
    }
    ((float2*)(dst + (size_t)gw * 64))[lane] = make_float2(ax, ay);
}

// ---------------- CSR edge aggregation (H=1, C=128) → d_out ----------------
__global__ void edgepass1_csr(const __half* __restrict__ hbuf,
                              float* __restrict__ outp) {
    int gw   = (blockIdx.x * blockDim.x + threadIdx.x) >> 5;
    int lane = threadIdx.x & 31;
    if (gw >= N_NODES) return;
    float iz = 1.0f / (g_Z[0] * g_Z[4] * g_Z[8]);  // undo scale Z0*Z1, divide by Z2
    int b = g_off[gw], eEnd = g_off[gw + 1];
    float x0 = 0.f, x1 = 0.f, x2 = 0.f, x3 = 0.f;
#pragma unroll 4
    for (int i = b; i < eEnd; i++) {
        int s = __ldg(&g_csr_src[i]);
        float a = __ldg(&g_r[i]) * iz;
        uint2 v = __ldg((const uint2*)(hbuf + (size_t)s * 128) + lane);
        float2 q0 = __half22float2(*(const __half2*)&v.x);
        float2 q1 = __half22float2(*(const __half2*)&v.y);
        x0 += a * q0.x; x1 += a * q0.y; x2 += a * q1.x; x3 += a * q1.y;
    }
    ((float4*)(outp + (size_t)gw * 128))[lane] = make_float4(x0, x1, x2, x3);
}

// ---------------- host -----------------------------------------------------
extern "C" void kernel_launch(void* const* d_in, const int* in_sizes, int n_in,
                              void* d_out, int out_size) {
    (void)in_sizes; (void)n_in; (void)out_size;
    const float* x     = (const float*)d_in[0];
    const int*   ei    = (const int*)  d_in[1];
    const float* eattr = (const float*)d_in[2];
    const int*   jt    = (const int*)  d_in[3];
    const float* emb   = (const float*)d_in[4];
    const float* W0    = (const float*)d_in[5];
    const float* as0   = (const float*)d_in[6];
    const float* ad0   = (const float*)d_in[7];
    const float* We0   = (const float*)d_in[8];
    const float* W1    = (const float*)d_in[9];
    const float* as1   = (const float*)d_in[10];
    const float* ad1   = (const float*)d_in[11];
    const float* We1   = (const float*)d_in[12];
    const float* W2    = (const float*)d_in[13];
    const float* as2   = (const float*)d_in[14];
    const float* ad2   = (const float*)d_in[15];
    const float* We2   = (const float*)d_in[16];
    float* out = (float*)d_out;

    float *p_feat0, *p_accum;
    __half *p_hh;
    cudaGetSymbolAddress((void**)&p_feat0, g_feat0);
    cudaGetSymbolAddress((void**)&p_hh,    g_hh);
    cudaGetSymbolAddress((void**)&p_accum, g_accum);

    const int GEMM_BLOCKS = N_NODES / 25;                // 2000, exact
    const int EP_BLOCKS = (N_NODES * 32 + TB - 1) / TB;  // warp per node
    const int SW_BLOCKS = 2048;

    // CSR build + feature prep + p-vector precompute (3 launches)
    feat0hist_kernel<<<(W_P2 + TB - 1) / TB, TB>>>(x, jt, emb, ei,
                                                   W0, as0, ad0,
                                                   W1, as1, ad1,
                                                   W2, as2, ad2);
    scan_kernel<<<1, 1024>>>();
    scatter_kernel<<<(E_TOT + TB - 1) / TB, TB>>>(ei);

    // ---- layer 0 (H=4, C=64, IN=20); h scale 256 ----
    gemm_s4_kernel<IN0, 20, false, 0, -1><<<GEMM_BLOCKS, 256>>>(p_feat0, W0, p_hh);
    scoresum4_kernel<<<SW_BLOCKS, TB>>>(ei, eattr, We0, 0);
    edgepass4_csr<-1><<<EP_BLOCKS, TB>>>(p_hh, p_accum, 0);

    // ---- layer 1 (H=4, C=64, IN=64); ELU fused; h scale Z0; CH=16 for occ --
    gemm_s4_kernel<HID, 16, true, 80, 0><<<GEMM_BLOCKS, 256>>>(p_accum, W1, p_hh);
    scoresum4_kernel<<<SW_BLOCKS, TB>>>(ei, eattr, We1, 4);
    edgepass4_csr<0><<<EP_BLOCKS, TB>>>(p_hh, p_accum, 4);

    // ---- layer 2 (H=1, C=128, IN=64); ELU fused; h scale Z0*Z1; CH=32 ------
    gemm_s1_kernel<HID, 32, true, 336><<<GEMM_BLOCKS, 128>>>(p_accum, W2, p_hh);
    scoresum1_kernel<<<SW_BLOCKS, TB>>>(ei, eattr, We2, 8);
    edgepass1_csr<<<EP_BLOCKS, TB>>>(p_hh, out);
}